// round 12
// baseline (speedup 1.0000x reference)
#include <cuda_runtime.h>

#define NN 100000
#define EMAX 1600000
#define SCAN_B 1024
#define SCAN_NB ((NN + SCAN_B - 1) / SCAN_B)   // 98

// ---- scratch (device globals; no runtime allocation allowed) ----
__device__ int      g_deg[NN];
__device__ int      g_off[NN + 1];
__device__ int      g_cur[NN];
__device__ int      g_csr[EMAX + NN];   // src node per CSR slot (sorted by dst)
__device__ float    g_ha[NN * 64];      // h ping
__device__ float    g_hb[NN * 64];      // h pong
__device__ float    g_esa[NN * 4], g_eda[NN * 4];   // es/ed ping
__device__ float    g_esb[NN * 4], g_edb[NN * 4];   // es/ed pong
__device__ unsigned g_gmax[12];         // per-layer per-head global max of es
__device__ int      g_bsum[SCAN_NB];

__device__ __forceinline__ unsigned fenc(float f) {
    unsigned u = __float_as_uint(f);
    return u ^ ((u & 0x80000000u) ? 0xFFFFFFFFu : 0x80000000u);
}
__device__ __forceinline__ float fdec(unsigned e) {
    unsigned u = e ^ ((e & 0x80000000u) ? 0x80000000u : 0xFFFFFFFFu);
    return __uint_as_float(u);
}
__device__ __forceinline__ float leaky02(float e) {
    return (e > 0.f) ? e : 0.2f * e;
}

// ------------------------------------------------------------------
// CSR construction
// ------------------------------------------------------------------
__global__ void k_init_deg() {
    int i = blockIdx.x * blockDim.x + threadIdx.x;
    if (i < NN) g_deg[i] = 1;           // self-loop
    if (i < 12) g_gmax[i] = 0u;
}

__global__ void k_hist(const int* __restrict__ dst, int E) {
    int i = blockIdx.x * blockDim.x + threadIdx.x;
    if (i < E) atomicAdd(&g_deg[dst[i]], 1);
}

__global__ void k_scan1() {
    __shared__ int red[8];
    int b = blockIdx.x, t = threadIdx.x;
    int s = 0;
    #pragma unroll
    for (int j = 0; j < 4; j++) {
        int idx = b * SCAN_B + j * 256 + t;
        if (idx < NN) s += g_deg[idx];
    }
    #pragma unroll
    for (int o = 16; o >= 1; o >>= 1) s += __shfl_down_sync(0xffffffffu, s, o);
    if ((t & 31) == 0) red[t >> 5] = s;
    __syncthreads();
    if (t == 0) {
        int tot = 0;
        #pragma unroll
        for (int w = 0; w < 8; w++) tot += red[w];
        g_bsum[b] = tot;
    }
}

// scan3: per-block offset from g_bsum (no scan2), local scan, plant self-loop
__global__ void k_scan3() {
    __shared__ int sh[SCAN_B];
    __shared__ int redsum[32];
    __shared__ int s_bo;
    int b = blockIdx.x, t = threadIdx.x;
    {
        int v = (t < SCAN_NB && t < b) ? g_bsum[t] : 0;
        #pragma unroll
        for (int o = 16; o >= 1; o >>= 1) v += __shfl_down_sync(0xffffffffu, v, o);
        if ((t & 31) == 0) redsum[t >> 5] = v;
        __syncthreads();
        if (t == 0) {
            int s = 0;
            #pragma unroll
            for (int w = 0; w < 32; w++) s += redsum[w];
            s_bo = s;
        }
        __syncthreads();
    }
    int bo = s_bo;

    int i = b * SCAN_B + t;
    int v = (i < NN) ? g_deg[i] : 0;
    sh[t] = v;
    __syncthreads();
    for (int o = 1; o < SCAN_B; o <<= 1) {
        int u = (t >= o) ? sh[t - o] : 0;
        __syncthreads();
        sh[t] += u;
        __syncthreads();
    }
    if (i < NN) {
        int ex = sh[t] - v + bo;
        g_off[i] = ex;
        g_csr[ex] = i;          // self-loop first
        g_cur[i] = ex + 1;
    }
    if (b == SCAN_NB - 1 && t == SCAN_B - 1)
        g_off[NN] = bo + sh[SCAN_B - 1];
}

__global__ void k_fill(const int* __restrict__ src, const int* __restrict__ dst, int E) {
    int i = blockIdx.x * blockDim.x + threadIdx.x;
    if (i >= E) return;
    int s = src[i], d = dst[i];
    int p = atomicAdd(&g_cur[d], 1);
    g_csr[p] = s;
}

// ------------------------------------------------------------------
// Layer-0 transform (Fin=1): h0 = x*W0 -> g_ha, es/ed -> a-buffers
// 4 nodes per warp.
// ------------------------------------------------------------------
__global__ __launch_bounds__(256) void k_transform0(
    const float* __restrict__ x,
    const float* __restrict__ Wg,
    const float* __restrict__ avs,
    const float* __restrict__ avd)
{
    __shared__ float Ws[64];
    __shared__ float As[64], Ad[64];
    __shared__ unsigned bmax[4];
    int t = threadIdx.x;
    if (t < 64) { Ws[t] = Wg[t]; As[t] = avs[t]; Ad[t] = avd[t]; }
    if (t < 4)  bmax[t] = 0u;
    __syncthreads();

    int lane = t & 31;
    int c0   = lane * 2;
    int n0 = blockIdx.x * 32 + (t >> 5) * 4;

    #pragma unroll
    for (int r = 0; r < 4; r++) {
        int n = n0 + r;
        float xv = __ldg(x + n);
        float a0 = xv * Ws[c0];
        float a1 = xv * Ws[c0 + 1];
        float2 hv2; hv2.x = a0; hv2.y = a1;
        *(float2*)(g_ha + (size_t)n * 64 + c0) = hv2;
        float ps = a0 * As[c0] + a1 * As[c0 + 1];
        float pd = a0 * Ad[c0] + a1 * Ad[c0 + 1];
        #pragma unroll
        for (int o = 4; o >= 1; o >>= 1) {
            ps += __shfl_down_sync(0xffffffffu, ps, o);
            pd += __shfl_down_sync(0xffffffffu, pd, o);
        }
        if ((lane & 7) == 0) {
            int hd = lane >> 3;
            g_esa[n * 4 + hd] = ps;
            g_eda[n * 4 + hd] = pd;
            atomicMax(&bmax[hd], fenc(ps));
        }
    }
    __syncthreads();
    if (t < 4) atomicMax(&g_gmax[t], bmax[t]);
}

// ------------------------------------------------------------------
// Half-warp (16-lane) single-pass softmax aggregation (R9-proven),
// parameterized over input buffers.
// ------------------------------------------------------------------
__device__ __forceinline__ float4 agg_node16(
    int n, int l16, int hb, unsigned hmask, int layer,
    const float* __restrict__ bias,
    const float* __restrict__ hbuf,
    const float* __restrict__ esb,
    const float* __restrict__ edb)
{
    int hd = l16 >> 2;
    int q0 = l16 * 4;
    int beg = __ldg(&g_off[n]), end = __ldg(&g_off[n + 1]);
    float edv = __ldg(&edb[n * 4 + hd]);
    float m = leaky02(fdec(g_gmax[layer * 4 + hd]) + edv);

    float s = 0.f;
    float a0 = 0.f, a1 = 0.f, a2 = 0.f, a3 = 0.f;
    for (int base = beg; base < end; base += 16) {
        int rem = end - base;
        int cnt = rem < 16 ? rem : 16;
        int safel = l16 < rem ? l16 : 0;
        int myidx = __ldg(&g_csr[base + safel]);   // coalesced 64B, 16 edges
        int j = 0;
        for (; j + 8 <= cnt; j += 8) {
            int sc[8]; float ev[8]; float4 hv[8];
            #pragma unroll
            for (int q = 0; q < 8; q++)
                sc[q] = __shfl_sync(hmask, myidx, hb + j + q);
            #pragma unroll
            for (int q = 0; q < 8; q++) {
                ev[q] = __ldg(&esb[sc[q] * 4 + hd]);
                hv[q] = __ldg((const float4*)(hbuf + (size_t)sc[q] * 64 + q0));
            }
            #pragma unroll
            for (int q = 0; q < 8; q++) {
                float w = __expf(leaky02(ev[q] + edv) - m);
                s  += w;
                a0 += w * hv[q].x; a1 += w * hv[q].y;
                a2 += w * hv[q].z; a3 += w * hv[q].w;
            }
        }
        if (j + 4 <= cnt) {
            int sc[4]; float ev[4]; float4 hv[4];
            #pragma unroll
            for (int q = 0; q < 4; q++)
                sc[q] = __shfl_sync(hmask, myidx, hb + j + q);
            #pragma unroll
            for (int q = 0; q < 4; q++) {
                ev[q] = __ldg(&esb[sc[q] * 4 + hd]);
                hv[q] = __ldg((const float4*)(hbuf + (size_t)sc[q] * 64 + q0));
            }
            #pragma unroll
            for (int q = 0; q < 4; q++) {
                float w = __expf(leaky02(ev[q] + edv) - m);
                s  += w;
                a0 += w * hv[q].x; a1 += w * hv[q].y;
                a2 += w * hv[q].z; a3 += w * hv[q].w;
            }
            j += 4;
        }
        for (; j < cnt; j++) {
            int sc = __shfl_sync(hmask, myidx, hb + j);
            float  e  = __ldg(&esb[sc * 4 + hd]);
            float4 hv = __ldg((const float4*)(hbuf + (size_t)sc * 64 + q0));
            float w = __expf(leaky02(e + edv) - m);
            s  += w;
            a0 += w * hv.x; a1 += w * hv.y;
            a2 += w * hv.z; a3 += w * hv.w;
        }
    }
    float inv = 1.f / (s + 1e-16f);
    float4 bv = __ldg((const float4*)(bias + q0));
    float4 o;
    o.x = a0 * inv + bv.x;
    o.y = a1 * inv + bv.y;
    o.z = a2 * inv + bv.z;
    o.w = a3 * inv + bv.w;
    return o;
}

// ------------------------------------------------------------------
// Fused: aggregate(layer) + transform(layer+1) epilogue.
// 512 threads = 32 half-warps = 32 nodes per block (3125 blocks exact).
// pin=0: read a-buffers, write b-buffers; pin=1: opposite.
// ------------------------------------------------------------------
__global__ __launch_bounds__(512) void k_agg_trf(
    const float* __restrict__ bias, int layer, int pin,
    const float* __restrict__ Wg,
    const float* __restrict__ avs,
    const float* __restrict__ avd)
{
    __shared__ float Ws[64 * 64];
    __shared__ float As[64], Ad[64];
    __shared__ unsigned bmax[4];
    __shared__ float t1s[32][68];

    const float* hin  = pin ? g_hb  : g_ha;
    const float* esin = pin ? g_esb : g_esa;
    const float* edin = pin ? g_edb : g_eda;
    float* hout  = pin ? g_ha  : g_hb;
    float* esout = pin ? g_esa : g_esb;
    float* edout = pin ? g_eda : g_edb;

    int t = threadIdx.x;
    {
        const float4* W4 = (const float4*)Wg;
        float4* Ws4 = (float4*)Ws;
        for (int i = t; i < 64 * 16; i += blockDim.x) Ws4[i] = __ldg(W4 + i);
    }
    if (t < 64) { As[t] = avs[t]; Ad[t] = avd[t]; }
    if (t < 4)  bmax[t] = 0u;
    __syncthreads();

    int lane = t & 31;
    int l16  = lane & 15;
    int hb   = lane & 16;
    unsigned hmask = 0xFFFFu << hb;
    int hid  = t >> 4;                  // 0..31
    int q0   = l16 * 4;
    int n = blockIdx.x * 32 + hid;      // exact: 3125*32 = 100000

    // ---- aggregate layer L ----
    float4 xr = agg_node16(n, l16, hb, hmask, layer, bias, hin, esin, edin);
    *(float4*)(&t1s[hid][q0]) = xr;
    __syncwarp();

    // ---- transform L+1: row @ W, lane owns 4 output channels ----
    float a0 = 0.f, a1 = 0.f, a2 = 0.f, a3 = 0.f;
    #pragma unroll
    for (int k = 0; k < 64; k++) {
        float xv = t1s[hid][k];
        float4 wv = *(const float4*)(Ws + k * 64 + q0);
        a0 += xv * wv.x; a1 += xv * wv.y;
        a2 += xv * wv.z; a3 += xv * wv.w;
    }
    float4 hv4; hv4.x = a0; hv4.y = a1; hv4.z = a2; hv4.w = a3;
    *(float4*)(hout + (size_t)n * 64 + q0) = hv4;

    // ---- es/ed dots for L+1: partial over own 4 channels, reduce over head group ----
    float ps = a0 * As[q0] + a1 * As[q0 + 1] + a2 * As[q0 + 2] + a3 * As[q0 + 3];
    float pd = a0 * Ad[q0] + a1 * Ad[q0 + 1] + a2 * Ad[q0 + 2] + a3 * Ad[q0 + 3];
    ps += __shfl_down_sync(0xffffffffu, ps, 2);
    pd += __shfl_down_sync(0xffffffffu, pd, 2);
    ps += __shfl_down_sync(0xffffffffu, ps, 1);
    pd += __shfl_down_sync(0xffffffffu, pd, 1);
    if ((l16 & 3) == 0) {
        int hd = l16 >> 2;
        esout[n * 4 + hd] = ps;
        edout[n * 4 + hd] = pd;
        atomicMax(&bmax[hd], fenc(ps));
    }
    __syncthreads();
    if (t < 4) atomicMax(&g_gmax[(layer + 1) * 4 + t], bmax[t]);
}

// ------------------------------------------------------------------
// Layer-2 aggregate fused with MLP + decoder + softmax.
// 512 threads = 32 nodes per block.
// ------------------------------------------------------------------
__global__ __launch_bounds__(512) void k_agg_mlp(
    const float* __restrict__ bias, int layer, int pin,
    const float* __restrict__ lw1, const float* __restrict__ lb1,
    const float* __restrict__ lw2, const float* __restrict__ lb2,
    const float* __restrict__ dw,  const float* __restrict__ db,
    float* __restrict__ out)
{
    __shared__ float W1s[64 * 64];
    __shared__ float W2s[64 * 16];
    __shared__ float b1s[64], b2s[16], dws[64], dbs[4];
    __shared__ float t1s[32][68];
    __shared__ float t2s[32][16];
    __shared__ float lgs[32][4];

    const float* hin  = pin ? g_hb  : g_ha;
    const float* esin = pin ? g_esb : g_esa;
    const float* edin = pin ? g_edb : g_eda;

    int t = threadIdx.x;
    {
        const float4* W14 = (const float4*)lw1;
        float4* W1s4 = (float4*)W1s;
        for (int i = t; i < 64 * 16; i += blockDim.x) W1s4[i] = __ldg(W14 + i);
        const float4* W24 = (const float4*)lw2;
        float4* W2s4 = (float4*)W2s;
        for (int i = t; i < 16 * 16; i += blockDim.x) W2s4[i] = __ldg(W24 + i);
    }
    if (t < 64) b1s[t] = lb1[t];
    if (t < 16) b2s[t] = lb2[t];
    if (t < 64) dws[t] = dw[t];
    if (t < 4)  dbs[t] = db[t];
    __syncthreads();

    int lane = t & 31;
    int l16  = lane & 15;
    int hb   = lane & 16;
    unsigned hmask = 0xFFFFu << hb;
    int hid  = t >> 4;                  // 0..31
    int q0   = l16 * 4;
    int n = blockIdx.x * 32 + hid;      // exact

    // ---- layer-2 aggregation ----
    float4 xr = agg_node16(n, l16, hb, hmask, layer, bias, hin, esin, edin);
    *(float4*)(&t1s[hid][q0]) = xr;
    __syncwarp();

    // ---- Linear(64,64) + ReLU ----
    float a0 = b1s[q0], a1 = b1s[q0 + 1], a2 = b1s[q0 + 2], a3 = b1s[q0 + 3];
    #pragma unroll
    for (int k = 0; k < 64; k++) {
        float xv = t1s[hid][k];
        float4 wv = *(const float4*)(W1s + k * 64 + q0);
        a0 += xv * wv.x; a1 += xv * wv.y;
        a2 += xv * wv.z; a3 += xv * wv.w;
    }
    a0 = a0 > 0.f ? a0 : 0.f;
    a1 = a1 > 0.f ? a1 : 0.f;
    a2 = a2 > 0.f ? a2 : 0.f;
    a3 = a3 > 0.f ? a3 : 0.f;
    __syncwarp();
    t1s[hid][q0]     = a0;
    t1s[hid][q0 + 1] = a1;
    t1s[hid][q0 + 2] = a2;
    t1s[hid][q0 + 3] = a3;
    __syncwarp();

    // ---- Linear(64,16) ----
    {
        float acc = b2s[l16];
        #pragma unroll
        for (int k = 0; k < 64; k++) acc += t1s[hid][k] * W2s[k * 16 + l16];
        t2s[hid][l16] = acc;
    }
    __syncwarp();

    // ---- decoder Linear(16,4) ----
    if (l16 < 4) {
        float lg = dbs[l16];
        #pragma unroll
        for (int i = 0; i < 16; i++) lg += t2s[hid][i] * dws[i * 4 + l16];
        lgs[hid][l16] = lg;
    }
    __syncwarp();

    // ---- softmax over 4 logits ----
    if (l16 < 4) {
        float l0 = lgs[hid][0], l1 = lgs[hid][1], l2 = lgs[hid][2], l3 = lgs[hid][3];
        float mx = fmaxf(fmaxf(l0, l1), fmaxf(l2, l3));
        float e0 = __expf(l0 - mx), e1 = __expf(l1 - mx);
        float e2 = __expf(l2 - mx), e3 = __expf(l3 - mx);
        float den = e0 + e1 + e2 + e3;
        float mine = (l16 == 0) ? e0 : (l16 == 1) ? e1 : (l16 == 2) ? e2 : e3;
        out[(size_t)n * 4 + l16] = mine / den;
    }
}

// ------------------------------------------------------------------
extern "C" void kernel_launch(void* const* d_in, const int* in_sizes, int n_in,
                              void* d_out, int out_size)
{
    const float* x   = (const float*)d_in[0];
    const int*   ei  = (const int*)  d_in[1];
    int E = in_sizes[1] / 2;
    const int* src = ei;
    const int* dst = ei + E;
    const float* W0  = (const float*)d_in[2];
    const float* as0 = (const float*)d_in[3];
    const float* ad0 = (const float*)d_in[4];
    const float* b0  = (const float*)d_in[5];
    const float* W1  = (const float*)d_in[6];
    const float* as1 = (const float*)d_in[7];
    const float* ad1 = (const float*)d_in[8];
    const float* b1  = (const float*)d_in[9];
    const float* W2  = (const float*)d_in[10];
    const float* as2 = (const float*)d_in[11];
    const float* ad2 = (const float*)d_in[12];
    const float* b2  = (const float*)d_in[13];
    const float* lw1 = (const float*)d_in[14];
    const float* lb1 = (const float*)d_in[15];
    const float* lw2 = (const float*)d_in[16];
    const float* lb2 = (const float*)d_in[17];
    const float* dw  = (const float*)d_in[18];
    const float* db  = (const float*)d_in[19];
    float* out = (float*)d_out;

    const int N32_BLOCKS = NN / 32;     // 3125, exact
    const int NT512 = 512;

    // CSR build
    k_init_deg<<<(NN + 255) / 256, 256>>>();
    k_hist<<<(E + 255) / 256, 256>>>(dst, E);
    k_scan1<<<SCAN_NB, 256>>>();
    k_scan3<<<SCAN_NB, SCAN_B>>>();
    k_fill<<<(E + 255) / 256, 256>>>(src, dst, E);

    // Layer 0 transform (Fin=1): x -> h0 (a-buffers)
    k_transform0<<<N32_BLOCKS, 256>>>(x, W0, as0, ad0);
    // Fused: aggregate L0 + transform L1  (a -> b)
    k_agg_trf<<<N32_BLOCKS, NT512>>>(b0, 0, 0, W1, as1, ad1);
    // Fused: aggregate L1 + transform L2  (b -> a)
    k_agg_trf<<<N32_BLOCKS, NT512>>>(b1, 1, 1, W2, as2, ad2);
    // Aggregate L2 + MLP + decoder + softmax  (a -> out)
    k_agg_mlp<<<N32_BLOCKS, NT512>>>(b2, 2, 0, lw1, lb1, lw2, lb2, dw, db, out);
}

// round 13
// speedup vs baseline: 1.1026x; 1.1026x over previous
#include <cuda_runtime.h>

#define NN 100000
#define EMAX 1600000
#define SCAN_B 1024
#define SCAN_NB ((NN + SCAN_B - 1) / SCAN_B)   // 98

// ---- scratch (device globals; no runtime allocation allowed) ----
__device__ int      g_deg[NN];          // zero at load; re-zeroed by k_scan3 each launch
__device__ int      g_off[NN + 1];
__device__ int      g_cur[NN];
__device__ int      g_csr[EMAX + NN];   // src node per CSR slot (sorted by dst)
__device__ float    g_h [NN * 64];      // transformed features for current layer
__device__ float    g_fa[NN * 64];      // ping
__device__ float    g_fb[NN * 64];      // pong
__device__ float    g_es[NN * 4];       // per-node source attention logits
__device__ float    g_ed[NN * 4];       // per-node dest attention logits
__device__ unsigned g_gmax[12];         // monotone across replays (same values each run)
__device__ int      g_bsum[SCAN_NB];

__device__ __forceinline__ unsigned fenc(float f) {
    unsigned u = __float_as_uint(f);
    return u ^ ((u & 0x80000000u) ? 0xFFFFFFFFu : 0x80000000u);
}
__device__ __forceinline__ float fdec(unsigned e) {
    unsigned u = e ^ ((e & 0x80000000u) ? 0x80000000u : 0xFFFFFFFFu);
    return __uint_as_float(u);
}
__device__ __forceinline__ float leaky02(float e) {
    return (e > 0.f) ? e : 0.2f * e;
}

// ------------------------------------------------------------------
// CSR construction (self-loop accounted as implicit +1 in the scans;
// g_deg holds edge-only counts and is re-zeroed by scan3 for replay)
// ------------------------------------------------------------------
__global__ void k_hist(const int* __restrict__ dst, int E) {
    int i4 = (blockIdx.x * blockDim.x + threadIdx.x) * 4;
    if (i4 + 4 <= E) {
        int4 d = __ldg((const int4*)(dst + i4));
        atomicAdd(&g_deg[d.x], 1);
        atomicAdd(&g_deg[d.y], 1);
        atomicAdd(&g_deg[d.z], 1);
        atomicAdd(&g_deg[d.w], 1);
    } else {
        for (int i = i4; i < E; i++) atomicAdd(&g_deg[__ldg(dst + i)], 1);
    }
}

__global__ void k_scan1() {
    __shared__ int red[8];
    int b = blockIdx.x, t = threadIdx.x;
    int s = 0;
    #pragma unroll
    for (int j = 0; j < 4; j++) {
        int idx = b * SCAN_B + j * 256 + t;
        if (idx < NN) s += g_deg[idx] + 1;        // +1 self-loop
    }
    #pragma unroll
    for (int o = 16; o >= 1; o >>= 1) s += __shfl_down_sync(0xffffffffu, s, o);
    if ((t & 31) == 0) red[t >> 5] = s;
    __syncthreads();
    if (t == 0) {
        int tot = 0;
        #pragma unroll
        for (int w = 0; w < 8; w++) tot += red[w];
        g_bsum[b] = tot;
    }
}

// scan3: per-block offset from g_bsum, local scan, plant self-loop,
// and re-zero g_deg for the next replay.
__global__ void k_scan3() {
    __shared__ int sh[SCAN_B];
    __shared__ int redsum[32];
    __shared__ int s_bo;
    int b = blockIdx.x, t = threadIdx.x;
    {
        int v = (t < SCAN_NB && t < b) ? g_bsum[t] : 0;
        #pragma unroll
        for (int o = 16; o >= 1; o >>= 1) v += __shfl_down_sync(0xffffffffu, v, o);
        if ((t & 31) == 0) redsum[t >> 5] = v;
        __syncthreads();
        if (t == 0) {
            int s = 0;
            #pragma unroll
            for (int w = 0; w < 32; w++) s += redsum[w];
            s_bo = s;
        }
        __syncthreads();
    }
    int bo = s_bo;

    int i = b * SCAN_B + t;
    int v = 0;
    if (i < NN) {
        v = g_deg[i] + 1;       // +1 self-loop
        g_deg[i] = 0;           // reset for next replay
    }
    sh[t] = v;
    __syncthreads();
    for (int o = 1; o < SCAN_B; o <<= 1) {
        int u = (t >= o) ? sh[t - o] : 0;
        __syncthreads();
        sh[t] += u;
        __syncthreads();
    }
    if (i < NN) {
        int ex = sh[t] - v + bo;
        g_off[i] = ex;
        g_csr[ex] = i;          // self-loop first
        g_cur[i] = ex + 1;
    }
    if (b == SCAN_NB - 1 && t == SCAN_B - 1)
        g_off[NN] = bo + sh[SCAN_B - 1];
}

// ------------------------------------------------------------------
// Fused launch: blocks [0, FB) fill CSR edges (int4, 4 edges/thread);
// blocks [FB, FB+NN/32) run the layer-0 transform (Fin=1).
// Both depend only on scan3; they are mutually independent.
// ------------------------------------------------------------------
__global__ __launch_bounds__(256) void k_fill_trf0(
    const int* __restrict__ src, const int* __restrict__ dst, int E, int FB,
    const float* __restrict__ x,
    const float* __restrict__ Wg,
    const float* __restrict__ avs,
    const float* __restrict__ avd)
{
    if (blockIdx.x < FB) {
        int i4 = (blockIdx.x * blockDim.x + threadIdx.x) * 4;
        if (i4 + 4 <= E) {
            int4 s = __ldg((const int4*)(src + i4));
            int4 d = __ldg((const int4*)(dst + i4));
            g_csr[atomicAdd(&g_cur[d.x], 1)] = s.x;
            g_csr[atomicAdd(&g_cur[d.y], 1)] = s.y;
            g_csr[atomicAdd(&g_cur[d.z], 1)] = s.z;
            g_csr[atomicAdd(&g_cur[d.w], 1)] = s.w;
        } else {
            for (int i = i4; i < E; i++) {
                int s = __ldg(src + i), d = __ldg(dst + i);
                g_csr[atomicAdd(&g_cur[d], 1)] = s;
            }
        }
        return;
    }

    // ---- layer-0 transform (Fin=1): 4 nodes per warp ----
    __shared__ float Ws[64];
    __shared__ float As[64], Ad[64];
    __shared__ unsigned bmax[4];
    int t = threadIdx.x;
    if (t < 64) { Ws[t] = Wg[t]; As[t] = avs[t]; Ad[t] = avd[t]; }
    if (t < 4)  bmax[t] = 0u;
    __syncthreads();

    int lane = t & 31;
    int c0   = lane * 2;
    int n0 = (blockIdx.x - FB) * 32 + (t >> 5) * 4;

    #pragma unroll
    for (int r = 0; r < 4; r++) {
        int n = n0 + r;
        if (n >= NN) break;
        float xv = __ldg(x + n);
        float a0 = xv * Ws[c0];
        float a1 = xv * Ws[c0 + 1];
        float2 hv2; hv2.x = a0; hv2.y = a1;
        *(float2*)(g_h + (size_t)n * 64 + c0) = hv2;
        float ps = a0 * As[c0] + a1 * As[c0 + 1];
        float pd = a0 * Ad[c0] + a1 * Ad[c0 + 1];
        #pragma unroll
        for (int o = 4; o >= 1; o >>= 1) {
            ps += __shfl_down_sync(0xffffffffu, ps, o);
            pd += __shfl_down_sync(0xffffffffu, pd, o);
        }
        if ((lane & 7) == 0) {
            int hd = lane >> 3;
            g_es[n * 4 + hd] = ps;
            g_ed[n * 4 + hd] = pd;
            atomicMax(&bmax[hd], fenc(ps));
        }
    }
    __syncthreads();
    if (t < 4) atomicMax(&g_gmax[t], bmax[t]);
}

// ------------------------------------------------------------------
// Node transform (Fin=64): 4 nodes per warp, hoisted W smem loads.
// xin_sel: 1 -> g_fa, 2 -> g_fb
// ------------------------------------------------------------------
__global__ __launch_bounds__(256) void k_transform(
    int xin_sel,
    const float* __restrict__ Wg,
    const float* __restrict__ avs,
    const float* __restrict__ avd,
    int layer)
{
    __shared__ float Ws[64 * 64];
    __shared__ float As[64], Ad[64];
    __shared__ unsigned bmax[4];
    const float* xin = (xin_sel == 1) ? g_fa : g_fb;
    int t = threadIdx.x;
    {
        const float4* W4 = (const float4*)Wg;
        float4* Ws4 = (float4*)Ws;
        for (int i = t; i < 64 * 16; i += blockDim.x) Ws4[i] = __ldg(W4 + i);
    }
    if (t < 64) { As[t] = avs[t]; Ad[t] = avd[t]; }
    if (t < 4)  bmax[t] = 0u;
    __syncthreads();

    int lane = t & 31;
    int c0   = lane * 2;
    int n0 = blockIdx.x * 32 + (t >> 5) * 4;
    int nv = NN - n0; if (nv > 4) nv = 4;

    float acc[4][2];
    #pragma unroll
    for (int r = 0; r < 4; r++) { acc[r][0] = 0.f; acc[r][1] = 0.f; }

    const float* x0p = xin + (size_t)n0 * 64;
    #pragma unroll
    for (int k = 0; k < 64; k += 4) {
        float2 w0 = *(const float2*)(Ws + (k + 0) * 64 + c0);
        float2 w1 = *(const float2*)(Ws + (k + 1) * 64 + c0);
        float2 w2 = *(const float2*)(Ws + (k + 2) * 64 + c0);
        float2 w3 = *(const float2*)(Ws + (k + 3) * 64 + c0);
        #pragma unroll
        for (int r = 0; r < 4; r++) {
            if (r < nv) {
                float4 xv = __ldg((const float4*)(x0p + r * 64 + k));
                acc[r][0] += xv.x * w0.x; acc[r][1] += xv.x * w0.y;
                acc[r][0] += xv.y * w1.x; acc[r][1] += xv.y * w1.y;
                acc[r][0] += xv.z * w2.x; acc[r][1] += xv.z * w2.y;
                acc[r][0] += xv.w * w3.x; acc[r][1] += xv.w * w3.y;
            }
        }
    }

    #pragma unroll
    for (int r = 0; r < 4; r++) {
        if (r >= nv) break;
        int n = n0 + r;
        float a0 = acc[r][0], a1 = acc[r][1];
        float2 hv2; hv2.x = a0; hv2.y = a1;
        *(float2*)(g_h + (size_t)n * 64 + c0) = hv2;
        float ps = a0 * As[c0] + a1 * As[c0 + 1];
        float pd = a0 * Ad[c0] + a1 * Ad[c0 + 1];
        #pragma unroll
        for (int o = 4; o >= 1; o >>= 1) {
            ps += __shfl_down_sync(0xffffffffu, ps, o);
            pd += __shfl_down_sync(0xffffffffu, pd, o);
        }
        if ((lane & 7) == 0) {
            int hd = lane >> 3;
            g_es[n * 4 + hd] = ps;
            g_ed[n * 4 + hd] = pd;
            atomicMax(&bmax[hd], fenc(ps));
        }
    }
    __syncthreads();
    if (t < 4) atomicMax(&g_gmax[layer * 4 + t], bmax[t]);
}

// ------------------------------------------------------------------
// Half-warp (16-lane) single-pass softmax aggregation (R9-proven).
// ------------------------------------------------------------------
__device__ __forceinline__ float4 agg_node16(
    int n, int l16, int hb, unsigned hmask, int layer,
    const float* __restrict__ bias)
{
    int hd = l16 >> 2;
    int q0 = l16 * 4;
    int beg = __ldg(&g_off[n]), end = __ldg(&g_off[n + 1]);
    float edv = __ldg(&g_ed[n * 4 + hd]);
    float m = leaky02(fdec(g_gmax[layer * 4 + hd]) + edv);

    float s = 0.f;
    float a0 = 0.f, a1 = 0.f, a2 = 0.f, a3 = 0.f;
    for (int base = beg; base < end; base += 16) {
        int rem = end - base;
        int cnt = rem < 16 ? rem : 16;
        int safel = l16 < rem ? l16 : 0;
        int myidx = __ldg(&g_csr[base + safel]);   // coalesced 64B, 16 edges
        int j = 0;
        for (; j + 8 <= cnt; j += 8) {
            int sc[8]; float ev[8]; float4 hv[8];
            #pragma unroll
            for (int q = 0; q < 8; q++)
                sc[q] = __shfl_sync(hmask, myidx, hb + j + q);
            #pragma unroll
            for (int q = 0; q < 8; q++) {
                ev[q] = __ldg(&g_es[sc[q] * 4 + hd]);
                hv[q] = __ldg((const float4*)(g_h + (size_t)sc[q] * 64 + q0));
            }
            #pragma unroll
            for (int q = 0; q < 8; q++) {
                float w = __expf(leaky02(ev[q] + edv) - m);
                s  += w;
                a0 += w * hv[q].x; a1 += w * hv[q].y;
                a2 += w * hv[q].z; a3 += w * hv[q].w;
            }
        }
        if (j + 4 <= cnt) {
            int sc[4]; float ev[4]; float4 hv[4];
            #pragma unroll
            for (int q = 0; q < 4; q++)
                sc[q] = __shfl_sync(hmask, myidx, hb + j + q);
            #pragma unroll
            for (int q = 0; q < 4; q++) {
                ev[q] = __ldg(&g_es[sc[q] * 4 + hd]);
                hv[q] = __ldg((const float4*)(g_h + (size_t)sc[q] * 64 + q0));
            }
            #pragma unroll
            for (int q = 0; q < 4; q++) {
                float w = __expf(leaky02(ev[q] + edv) - m);
                s  += w;
                a0 += w * hv[q].x; a1 += w * hv[q].y;
                a2 += w * hv[q].z; a3 += w * hv[q].w;
            }
            j += 4;
        }
        for (; j < cnt; j++) {
            int sc = __shfl_sync(hmask, myidx, hb + j);
            float  e  = __ldg(&g_es[sc * 4 + hd]);
            float4 hv = __ldg((const float4*)(g_h + (size_t)sc * 64 + q0));
            float w = __expf(leaky02(e + edv) - m);
            s  += w;
            a0 += w * hv.x; a1 += w * hv.y;
            a2 += w * hv.z; a3 += w * hv.w;
        }
    }
    float inv = 1.f / (s + 1e-16f);
    float4 bv = __ldg((const float4*)(bias + q0));
    float4 o;
    o.x = a0 * inv + bv.x;
    o.y = a1 * inv + bv.y;
    o.z = a2 * inv + bv.z;
    o.w = a3 * inv + bv.w;
    return o;
}

// ------------------------------------------------------------------
// Aggregation -> feature buffer (layers 0 and 1): half-warp per node
// ------------------------------------------------------------------
__global__ __launch_bounds__(256) void k_aggregate(
    const float* __restrict__ bias, int out_sel, int layer)
{
    float* xout = (out_sel == 1) ? g_fa : g_fb;
    int t    = threadIdx.x;
    int lane = t & 31;
    int l16  = lane & 15;
    int hb   = lane & 16;
    unsigned hmask = 0xFFFFu << hb;
    int n = blockIdx.x * 16 + (t >> 4);
    if (n >= NN) return;
    float4 o = agg_node16(n, l16, hb, hmask, layer, bias);
    *(float4*)(xout + (size_t)n * 64 + l16 * 4) = o;
}

// ------------------------------------------------------------------
// Layer-2 aggregate fused with MLP + decoder + softmax.
// Half-warp per node: 16 nodes per 256-thread block (R9-proven).
// ------------------------------------------------------------------
__global__ __launch_bounds__(256) void k_agg_mlp(
    const float* __restrict__ bias, int layer,
    const float* __restrict__ lw1, const float* __restrict__ lb1,
    const float* __restrict__ lw2, const float* __restrict__ lb2,
    const float* __restrict__ dw,  const float* __restrict__ db,
    float* __restrict__ out)
{
    __shared__ float W1s[64 * 64];
    __shared__ float W2s[64 * 16];
    __shared__ float b1s[64], b2s[16], dws[64], dbs[4];
    __shared__ float t1s[16][68];
    __shared__ float t2s[16][16];
    __shared__ float lgs[16][4];
    int t = threadIdx.x;
    {
        const float4* W14 = (const float4*)lw1;
        float4* W1s4 = (float4*)W1s;
        for (int i = t; i < 64 * 16; i += blockDim.x) W1s4[i] = __ldg(W14 + i);
        const float4* W24 = (const float4*)lw2;
        float4* W2s4 = (float4*)W2s;
        for (int i = t; i < 16 * 16; i += blockDim.x) W2s4[i] = __ldg(W24 + i);
    }
    if (t < 64) b1s[t] = lb1[t];
    if (t < 16) b2s[t] = lb2[t];
    if (t < 64) dws[t] = dw[t];
    if (t < 4)  dbs[t] = db[t];
    __syncthreads();

    int lane = t & 31;
    int l16  = lane & 15;
    int hb   = lane & 16;
    unsigned hmask = 0xFFFFu << hb;
    int hid  = t >> 4;
    int q0   = l16 * 4;
    int n = blockIdx.x * 16 + hid;
    if (n >= NN) return;

    float4 xr = agg_node16(n, l16, hb, hmask, layer, bias);
    *(float4*)(&t1s[hid][q0]) = xr;
    __syncwarp();

    float a0 = b1s[q0], a1 = b1s[q0 + 1], a2 = b1s[q0 + 2], a3 = b1s[q0 + 3];
    #pragma unroll
    for (int k = 0; k < 64; k++) {
        float xv = t1s[hid][k];
        float4 wv = *(const float4*)(W1s + k * 64 + q0);
        a0 += xv * wv.x; a1 += xv * wv.y;
        a2 += xv * wv.z; a3 += xv * wv.w;
    }
    a0 = a0 > 0.f ? a0 : 0.f;
    a1 = a1 > 0.f ? a1 : 0.f;
    a2 = a2 > 0.f ? a2 : 0.f;
    a3 = a3 > 0.f ? a3 : 0.f;
    __syncwarp();
    t1s[hid][q0]     = a0;
    t1s[hid][q0 + 1] = a1;
    t1s[hid][q0 + 2] = a2;
    t1s[hid][q0 + 3] = a3;
    __syncwarp();

    {
        float acc = b2s[l16];
        #pragma unroll
        for (int k = 0; k < 64; k++) acc += t1s[hid][k] * W2s[k * 16 + l16];
        t2s[hid][l16] = acc;
    }
    __syncwarp();

    if (l16 < 4) {
        float lg = dbs[l16];
        #pragma unroll
        for (int i = 0; i < 16; i++) lg += t2s[hid][i] * dws[i * 4 + l16];
        lgs[hid][l16] = lg;
    }
    __syncwarp();

    if (l16 < 4) {
        float l0 = lgs[hid][0], l1 = lgs[hid][1], l2 = lgs[hid][2], l3 = lgs[hid][3];
        float mx = fmaxf(fmaxf(l0, l1), fmaxf(l2, l3));
        float e0 = __expf(l0 - mx), e1 = __expf(l1 - mx);
        float e2 = __expf(l2 - mx), e3 = __expf(l3 - mx);
        float den = e0 + e1 + e2 + e3;
        float mine = (l16 == 0) ? e0 : (l16 == 1) ? e1 : (l16 == 2) ? e2 : e3;
        out[(size_t)n * 4 + l16] = mine / den;
    }
}

// ------------------------------------------------------------------
extern "C" void kernel_launch(void* const* d_in, const int* in_sizes, int n_in,
                              void* d_out, int out_size)
{
    const float* x   = (const float*)d_in[0];
    const int*   ei  = (const int*)  d_in[1];
    int E = in_sizes[1] / 2;
    const int* src = ei;
    const int* dst = ei + E;
    const float* W0  = (const float*)d_in[2];
    const float* as0 = (const float*)d_in[3];
    const float* ad0 = (const float*)d_in[4];
    const float* b0  = (const float*)d_in[5];
    const float* W1  = (const float*)d_in[6];
    const float* as1 = (const float*)d_in[7];
    const float* ad1 = (const float*)d_in[8];
    const float* b1  = (const float*)d_in[9];
    const float* W2  = (const float*)d_in[10];
    const float* as2 = (const float*)d_in[11];
    const float* ad2 = (const float*)d_in[12];
    const float* b2  = (const float*)d_in[13];
    const float* lw1 = (const float*)d_in[14];
    const float* lb1 = (const float*)d_in[15];
    const float* lw2 = (const float*)d_in[16];
    const float* lb2 = (const float*)d_in[17];
    const float* dw  = (const float*)d_in[18];
    const float* db  = (const float*)d_in[19];
    float* out = (float*)d_out;

    const int AGG16_BLOCKS = (NN + 15) / 16;  // half-warp per node
    const int TRF_BLOCKS   = (NN + 31) / 32;  // 4 nodes/warp, 8 warps/block
    const int NT = 256;
    int FB = (E / 4 + NT - 1) / NT + 1;       // fill blocks (4 edges/thread, +1 tail safety)

    // CSR build (g_deg is zero from prior replay's scan3 / module load)
    k_hist<<<FB, NT>>>(dst, E);
    k_scan1<<<SCAN_NB, 256>>>();
    k_scan3<<<SCAN_NB, SCAN_B>>>();
    // fill CSR edges + layer-0 transform in one launch (independent roles)
    k_fill_trf0<<<FB + TRF_BLOCKS, NT>>>(src, dst, E, FB, x, W0, as0, ad0);

    // GAT layer 0 aggregate -> g_fa
    k_aggregate<<<AGG16_BLOCKS, NT>>>(b0, 1, 0);
    // GAT layer 1: transform from g_fa, aggregate -> g_fb
    k_transform<<<TRF_BLOCKS, NT>>>(1, W1, as1, ad1, 1);
    k_aggregate<<<AGG16_BLOCKS, NT>>>(b1, 2, 1);
    // GAT layer 2: transform from g_fb, fused aggregate + MLP -> out
    k_transform<<<TRF_BLOCKS, NT>>>(2, W2, as2, ad2, 2);
    k_agg_mlp<<<AGG16_BLOCKS, NT>>>(b2, 2, lw1, lb1, lw2, lb2, dw, db, out);
}

// round 14
// speedup vs baseline: 1.1276x; 1.0227x over previous
#include <cuda_runtime.h>

#define NN 100000
#define EMAX 1600000
#define SCAN_B 1024
#define SCAN_NB ((NN + SCAN_B - 1) / SCAN_B)   // 98

// ---- scratch (device globals; no runtime allocation allowed) ----
__device__ int      g_deg[NN];          // zero at load; re-zeroed by k_scan3 each launch
__device__ int      g_off[NN + 1];
__device__ int      g_cur[NN];
__device__ int      g_csr[EMAX + NN];   // src node per CSR slot (sorted by dst)
__device__ float    g_h [NN * 64];      // transformed features for current layer
__device__ float    g_fa[NN * 64];      // ping
__device__ float    g_fb[NN * 64];      // pong
__device__ float    g_es[NN * 4];       // per-node source attention logits
__device__ float    g_ed[NN * 4];       // per-node dest attention logits
__device__ unsigned g_gmax[12];         // monotone across replays (same values each run)
__device__ int      g_bsum[SCAN_NB];

__device__ __forceinline__ unsigned fenc(float f) {
    unsigned u = __float_as_uint(f);
    return u ^ ((u & 0x80000000u) ? 0xFFFFFFFFu : 0x80000000u);
}
__device__ __forceinline__ float fdec(unsigned e) {
    unsigned u = e ^ ((e & 0x80000000u) ? 0x80000000u : 0xFFFFFFFFu);
    return __uint_as_float(u);
}
__device__ __forceinline__ float leaky02(float e) {
    return (e > 0.f) ? e : 0.2f * e;
}

// ------------------------------------------------------------------
// CSR construction
// ------------------------------------------------------------------
__global__ void k_hist(const int* __restrict__ dst, int E) {
    int i4 = (blockIdx.x * blockDim.x + threadIdx.x) * 4;
    if (i4 + 4 <= E) {
        int4 d = __ldg((const int4*)(dst + i4));
        atomicAdd(&g_deg[d.x], 1);
        atomicAdd(&g_deg[d.y], 1);
        atomicAdd(&g_deg[d.z], 1);
        atomicAdd(&g_deg[d.w], 1);
    } else {
        for (int i = i4; i < E; i++) atomicAdd(&g_deg[__ldg(dst + i)], 1);
    }
}

__global__ void k_scan1() {
    __shared__ int red[8];
    int b = blockIdx.x, t = threadIdx.x;
    int s = 0;
    #pragma unroll
    for (int j = 0; j < 4; j++) {
        int idx = b * SCAN_B + j * 256 + t;
        if (idx < NN) s += g_deg[idx] + 1;        // +1 self-loop
    }
    #pragma unroll
    for (int o = 16; o >= 1; o >>= 1) s += __shfl_down_sync(0xffffffffu, s, o);
    if ((t & 31) == 0) red[t >> 5] = s;
    __syncthreads();
    if (t == 0) {
        int tot = 0;
        #pragma unroll
        for (int w = 0; w < 8; w++) tot += red[w];
        g_bsum[b] = tot;
    }
}

__global__ void k_scan3() {
    __shared__ int sh[SCAN_B];
    __shared__ int redsum[32];
    __shared__ int s_bo;
    int b = blockIdx.x, t = threadIdx.x;
    {
        int v = (t < SCAN_NB && t < b) ? g_bsum[t] : 0;
        #pragma unroll
        for (int o = 16; o >= 1; o >>= 1) v += __shfl_down_sync(0xffffffffu, v, o);
        if ((t & 31) == 0) redsum[t >> 5] = v;
        __syncthreads();
        if (t == 0) {
            int s = 0;
            #pragma unroll
            for (int w = 0; w < 32; w++) s += redsum[w];
            s_bo = s;
        }
        __syncthreads();
    }
    int bo = s_bo;

    int i = b * SCAN_B + t;
    int v = 0;
    if (i < NN) {
        v = g_deg[i] + 1;       // +1 self-loop
        g_deg[i] = 0;           // reset for next replay
    }
    sh[t] = v;
    __syncthreads();
    for (int o = 1; o < SCAN_B; o <<= 1) {
        int u = (t >= o) ? sh[t - o] : 0;
        __syncthreads();
        sh[t] += u;
        __syncthreads();
    }
    if (i < NN) {
        int ex = sh[t] - v + bo;
        g_off[i] = ex;
        g_csr[ex] = i;          // self-loop first
        g_cur[i] = ex + 1;
    }
    if (b == SCAN_NB - 1 && t == SCAN_B - 1)
        g_off[NN] = bo + sh[SCAN_B - 1];
}

// ------------------------------------------------------------------
// Fused launch: blocks [0, FB) fill CSR edges; blocks [FB, ...) run the
// layer-0 transform (es/ed only; h0 never materialized — agg0 is rank-1).
// ------------------------------------------------------------------
__global__ __launch_bounds__(256) void k_fill_trf0(
    const int* __restrict__ src, const int* __restrict__ dst, int E, int FB,
    const float* __restrict__ x,
    const float* __restrict__ Wg,
    const float* __restrict__ avs,
    const float* __restrict__ avd)
{
    if (blockIdx.x < FB) {
        int i4 = (blockIdx.x * blockDim.x + threadIdx.x) * 4;
        if (i4 + 4 <= E) {
            int4 s = __ldg((const int4*)(src + i4));
            int4 d = __ldg((const int4*)(dst + i4));
            g_csr[atomicAdd(&g_cur[d.x], 1)] = s.x;
            g_csr[atomicAdd(&g_cur[d.y], 1)] = s.y;
            g_csr[atomicAdd(&g_cur[d.z], 1)] = s.z;
            g_csr[atomicAdd(&g_cur[d.w], 1)] = s.w;
        } else {
            for (int i = i4; i < E; i++) {
                int s = __ldg(src + i), d = __ldg(dst + i);
                g_csr[atomicAdd(&g_cur[d], 1)] = s;
            }
        }
        return;
    }

    // ---- layer-0 attention logits: es0[n,h] = x[n]*ka_h, ed0 = x[n]*kd_h
    // where ka_h = sum_c W0[h,c]*as0[h,c] (h0 = x*W0 is rank-1)
    __shared__ float Ws[64];
    __shared__ float As[64], Ad[64];
    __shared__ unsigned bmax[4];
    int t = threadIdx.x;
    if (t < 64) { Ws[t] = Wg[t]; As[t] = avs[t]; Ad[t] = avd[t]; }
    if (t < 4)  bmax[t] = 0u;
    __syncthreads();

    int lane = t & 31;
    int c0   = lane * 2;
    int n0 = (blockIdx.x - FB) * 32 + (t >> 5) * 4;

    #pragma unroll
    for (int r = 0; r < 4; r++) {
        int n = n0 + r;
        if (n >= NN) break;
        float xv = __ldg(x + n);
        float a0 = xv * Ws[c0];
        float a1 = xv * Ws[c0 + 1];
        float ps = a0 * As[c0] + a1 * As[c0 + 1];
        float pd = a0 * Ad[c0] + a1 * Ad[c0 + 1];
        #pragma unroll
        for (int o = 4; o >= 1; o >>= 1) {
            ps += __shfl_down_sync(0xffffffffu, ps, o);
            pd += __shfl_down_sync(0xffffffffu, pd, o);
        }
        if ((lane & 7) == 0) {
            int hd = lane >> 3;
            g_es[n * 4 + hd] = ps;
            g_ed[n * 4 + hd] = pd;
            atomicMax(&bmax[hd], fenc(ps));
        }
    }
    __syncthreads();
    if (t < 4) atomicMax(&g_gmax[t], bmax[t]);
}

// ------------------------------------------------------------------
// Layer-0 aggregate, rank-1 exact factorization:
// out0[n,c] = (sum_e alpha_e * x_src) * W0[c] + b0[c].
// Same half-warp/16-edge-chunk structure as the proven agg_node16,
// but the 256B h gather becomes a 4B broadcast x load.
// ------------------------------------------------------------------
__global__ __launch_bounds__(256) void k_agg0(
    const float* __restrict__ x,
    const float* __restrict__ W0,
    const float* __restrict__ b0)
{
    int t    = threadIdx.x;
    int lane = t & 31;
    int l16  = lane & 15;
    int hb   = lane & 16;
    unsigned hmask = 0xFFFFu << hb;
    int n = blockIdx.x * 16 + (t >> 4);
    if (n >= NN) return;

    int hd = l16 >> 2;
    int q0 = l16 * 4;
    int beg = __ldg(&g_off[n]), end = __ldg(&g_off[n + 1]);
    float edv = __ldg(&g_ed[n * 4 + hd]);
    float m = leaky02(fdec(g_gmax[hd]) + edv);

    float s = 0.f, ax = 0.f;
    for (int base = beg; base < end; base += 16) {
        int rem = end - base;
        int cnt = rem < 16 ? rem : 16;
        int safel = l16 < rem ? l16 : 0;
        int myidx = __ldg(&g_csr[base + safel]);
        int j = 0;
        for (; j + 8 <= cnt; j += 8) {
            int sc[8]; float ev[8], xs[8];
            #pragma unroll
            for (int q = 0; q < 8; q++)
                sc[q] = __shfl_sync(hmask, myidx, hb + j + q);
            #pragma unroll
            for (int q = 0; q < 8; q++) {
                ev[q] = __ldg(&g_es[sc[q] * 4 + hd]);
                xs[q] = __ldg(x + sc[q]);
            }
            #pragma unroll
            for (int q = 0; q < 8; q++) {
                float w = __expf(leaky02(ev[q] + edv) - m);
                s  += w;
                ax += w * xs[q];
            }
        }
        if (j + 4 <= cnt) {
            int sc[4]; float ev[4], xs[4];
            #pragma unroll
            for (int q = 0; q < 4; q++)
                sc[q] = __shfl_sync(hmask, myidx, hb + j + q);
            #pragma unroll
            for (int q = 0; q < 4; q++) {
                ev[q] = __ldg(&g_es[sc[q] * 4 + hd]);
                xs[q] = __ldg(x + sc[q]);
            }
            #pragma unroll
            for (int q = 0; q < 4; q++) {
                float w = __expf(leaky02(ev[q] + edv) - m);
                s  += w;
                ax += w * xs[q];
            }
            j += 4;
        }
        for (; j < cnt; j++) {
            int sc = __shfl_sync(hmask, myidx, hb + j);
            float e  = __ldg(&g_es[sc * 4 + hd]);
            float xv = __ldg(x + sc);
            float w = __expf(leaky02(e + edv) - m);
            s  += w;
            ax += w * xv;
        }
    }
    float val = ax / (s + 1e-16f);
    float4 w4 = __ldg((const float4*)(W0 + q0));
    float4 bv = __ldg((const float4*)(b0 + q0));
    float4 o;
    o.x = val * w4.x + bv.x;
    o.y = val * w4.y + bv.y;
    o.z = val * w4.z + bv.z;
    o.w = val * w4.w + bv.w;
    *(float4*)(g_fa + (size_t)n * 64 + q0) = o;
}

// ------------------------------------------------------------------
// Node transform (Fin=64): 4 nodes per warp, hoisted W smem loads.
// xin_sel: 1 -> g_fa, 2 -> g_fb
// ------------------------------------------------------------------
__global__ __launch_bounds__(256) void k_transform(
    int xin_sel,
    const float* __restrict__ Wg,
    const float* __restrict__ avs,
    const float* __restrict__ avd,
    int layer)
{
    __shared__ float Ws[64 * 64];
    __shared__ float As[64], Ad[64];
    __shared__ unsigned bmax[4];
    const float* xin = (xin_sel == 1) ? g_fa : g_fb;
    int t = threadIdx.x;
    {
        const float4* W4 = (const float4*)Wg;
        float4* Ws4 = (float4*)Ws;
        for (int i = t; i < 64 * 16; i += blockDim.x) Ws4[i] = __ldg(W4 + i);
    }
    if (t < 64) { As[t] = avs[t]; Ad[t] = avd[t]; }
    if (t < 4)  bmax[t] = 0u;
    __syncthreads();

    int lane = t & 31;
    int c0   = lane * 2;
    int n0 = blockIdx.x * 32 + (t >> 5) * 4;
    int nv = NN - n0; if (nv > 4) nv = 4;

    float acc[4][2];
    #pragma unroll
    for (int r = 0; r < 4; r++) { acc[r][0] = 0.f; acc[r][1] = 0.f; }

    const float* x0p = xin + (size_t)n0 * 64;
    #pragma unroll
    for (int k = 0; k < 64; k += 4) {
        float2 w0 = *(const float2*)(Ws + (k + 0) * 64 + c0);
        float2 w1 = *(const float2*)(Ws + (k + 1) * 64 + c0);
        float2 w2 = *(const float2*)(Ws + (k + 2) * 64 + c0);
        float2 w3 = *(const float2*)(Ws + (k + 3) * 64 + c0);
        #pragma unroll
        for (int r = 0; r < 4; r++) {
            if (r < nv) {
                float4 xv = __ldg((const float4*)(x0p + r * 64 + k));
                acc[r][0] += xv.x * w0.x; acc[r][1] += xv.x * w0.y;
                acc[r][0] += xv.y * w1.x; acc[r][1] += xv.y * w1.y;
                acc[r][0] += xv.z * w2.x; acc[r][1] += xv.z * w2.y;
                acc[r][0] += xv.w * w3.x; acc[r][1] += xv.w * w3.y;
            }
        }
    }

    #pragma unroll
    for (int r = 0; r < 4; r++) {
        if (r >= nv) break;
        int n = n0 + r;
        float a0 = acc[r][0], a1 = acc[r][1];
        float2 hv2; hv2.x = a0; hv2.y = a1;
        *(float2*)(g_h + (size_t)n * 64 + c0) = hv2;
        float ps = a0 * As[c0] + a1 * As[c0 + 1];
        float pd = a0 * Ad[c0] + a1 * Ad[c0 + 1];
        #pragma unroll
        for (int o = 4; o >= 1; o >>= 1) {
            ps += __shfl_down_sync(0xffffffffu, ps, o);
            pd += __shfl_down_sync(0xffffffffu, pd, o);
        }
        if ((lane & 7) == 0) {
            int hd = lane >> 3;
            g_es[n * 4 + hd] = ps;
            g_ed[n * 4 + hd] = pd;
            atomicMax(&bmax[hd], fenc(ps));
        }
    }
    __syncthreads();
    if (t < 4) atomicMax(&g_gmax[layer * 4 + t], bmax[t]);
}

// ------------------------------------------------------------------
// Half-warp (16-lane) single-pass softmax aggregation (R9-proven).
// ------------------------------------------------------------------
__device__ __forceinline__ float4 agg_node16(
    int n, int l16, int hb, unsigned hmask, int layer,
    const float* __restrict__ bias)
{
    int hd = l16 >> 2;
    int q0 = l16 * 4;
    int beg = __ldg(&g_off[n]), end = __ldg(&g_off[n + 1]);
    float edv = __ldg(&g_ed[n * 4 + hd]);
    float m = leaky02(fdec(g_gmax[layer * 4 + hd]) + edv);

    float s = 0.f;
    float a0 = 0.f, a1 = 0.f, a2 = 0.f, a3 = 0.f;
    for (int base = beg; base < end; base += 16) {
        int rem = end - base;
        int cnt = rem < 16 ? rem : 16;
        int safel = l16 < rem ? l16 : 0;
        int myidx = __ldg(&g_csr[base + safel]);   // coalesced 64B, 16 edges
        int j = 0;
        for (; j + 8 <= cnt; j += 8) {
            int sc[8]; float ev[8]; float4 hv[8];
            #pragma unroll
            for (int q = 0; q < 8; q++)
                sc[q] = __shfl_sync(hmask, myidx, hb + j + q);
            #pragma unroll
            for (int q = 0; q < 8; q++) {
                ev[q] = __ldg(&g_es[sc[q] * 4 + hd]);
                hv[q] = __ldg((const float4*)(g_h + (size_t)sc[q] * 64 + q0));
            }
            #pragma unroll
            for (int q = 0; q < 8; q++) {
                float w = __expf(leaky02(ev[q] + edv) - m);
                s  += w;
                a0 += w * hv[q].x; a1 += w * hv[q].y;
                a2 += w * hv[q].z; a3 += w * hv[q].w;
            }
        }
        if (j + 4 <= cnt) {
            int sc[4]; float ev[4]; float4 hv[4];
            #pragma unroll
            for (int q = 0; q < 4; q++)
                sc[q] = __shfl_sync(hmask, myidx, hb + j + q);
            #pragma unroll
            for (int q = 0; q < 4; q++) {
                ev[q] = __ldg(&g_es[sc[q] * 4 + hd]);
                hv[q] = __ldg((const float4*)(g_h + (size_t)sc[q] * 64 + q0));
            }
            #pragma unroll
            for (int q = 0; q < 4; q++) {
                float w = __expf(leaky02(ev[q] + edv) - m);
                s  += w;
                a0 += w * hv[q].x; a1 += w * hv[q].y;
                a2 += w * hv[q].z; a3 += w * hv[q].w;
            }
            j += 4;
        }
        for (; j < cnt; j++) {
            int sc = __shfl_sync(hmask, myidx, hb + j);
            float  e  = __ldg(&g_es[sc * 4 + hd]);
            float4 hv = __ldg((const float4*)(g_h + (size_t)sc * 64 + q0));
            float w = __expf(leaky02(e + edv) - m);
            s  += w;
            a0 += w * hv.x; a1 += w * hv.y;
            a2 += w * hv.z; a3 += w * hv.w;
        }
    }
    float inv = 1.f / (s + 1e-16f);
    float4 bv = __ldg((const float4*)(bias + q0));
    float4 o;
    o.x = a0 * inv + bv.x;
    o.y = a1 * inv + bv.y;
    o.z = a2 * inv + bv.z;
    o.w = a3 * inv + bv.w;
    return o;
}

// ------------------------------------------------------------------
// Aggregation layer 1 -> g_fb: half-warp per node
// ------------------------------------------------------------------
__global__ __launch_bounds__(256) void k_aggregate(
    const float* __restrict__ bias, int layer)
{
    int t    = threadIdx.x;
    int lane = t & 31;
    int l16  = lane & 15;
    int hb   = lane & 16;
    unsigned hmask = 0xFFFFu << hb;
    int n = blockIdx.x * 16 + (t >> 4);
    if (n >= NN) return;
    float4 o = agg_node16(n, l16, hb, hmask, layer, bias);
    *(float4*)(g_fb + (size_t)n * 64 + l16 * 4) = o;
}

// ------------------------------------------------------------------
// Layer-2 aggregate fused with MLP + decoder + softmax.
// ------------------------------------------------------------------
__global__ __launch_bounds__(256) void k_agg_mlp(
    const float* __restrict__ bias, int layer,
    const float* __restrict__ lw1, const float* __restrict__ lb1,
    const float* __restrict__ lw2, const float* __restrict__ lb2,
    const float* __restrict__ dw,  const float* __restrict__ db,
    float* __restrict__ out)
{
    __shared__ float W1s[64 * 64];
    __shared__ float W2s[64 * 16];
    __shared__ float b1s[64], b2s[16], dws[64], dbs[4];
    __shared__ float t1s[16][68];
    __shared__ float t2s[16][16];
    __shared__ float lgs[16][4];
    int t = threadIdx.x;
    {
        const float4* W14 = (const float4*)lw1;
        float4* W1s4 = (float4*)W1s;
        for (int i = t; i < 64 * 16; i += blockDim.x) W1s4[i] = __ldg(W14 + i);
        const float4* W24 = (const float4*)lw2;
        float4* W2s4 = (float4*)W2s;
        for (int i = t; i < 16 * 16; i += blockDim.x) W2s4[i] = __ldg(W24 + i);
    }
    if (t < 64) b1s[t] = lb1[t];
    if (t < 16) b2s[t] = lb2[t];
    if (t < 64) dws[t] = dw[t];
    if (t < 4)  dbs[t] = db[t];
    __syncthreads();

    int lane = t & 31;
    int l16  = lane & 15;
    int hb   = lane & 16;
    unsigned hmask = 0xFFFFu << hb;
    int hid  = t >> 4;
    int q0   = l16 * 4;
    int n = blockIdx.x * 16 + hid;
    if (n >= NN) return;

    float4 xr = agg_node16(n, l16, hb, hmask, layer, bias);
    *(float4*)(&t1s[hid][q0]) = xr;
    __syncwarp();

    float a0 = b1s[q0], a1 = b1s[q0 + 1], a2 = b1s[q0 + 2], a3 = b1s[q0 + 3];
    #pragma unroll
    for (int k = 0; k < 64; k++) {
        float xv = t1s[hid][k];
        float4 wv = *(const float4*)(W1s + k * 64 + q0);
        a0 += xv * wv.x; a1 += xv * wv.y;
        a2 += xv * wv.z; a3 += xv * wv.w;
    }
    a0 = a0 > 0.f ? a0 : 0.f;
    a1 = a1 > 0.f ? a1 : 0.f;
    a2 = a2 > 0.f ? a2 : 0.f;
    a3 = a3 > 0.f ? a3 : 0.f;
    __syncwarp();
    t1s[hid][q0]     = a0;
    t1s[hid][q0 + 1] = a1;
    t1s[hid][q0 + 2] = a2;
    t1s[hid][q0 + 3] = a3;
    __syncwarp();

    {
        float acc = b2s[l16];
        #pragma unroll
        for (int k = 0; k < 64; k++) acc += t1s[hid][k] * W2s[k * 16 + l16];
        t2s[hid][l16] = acc;
    }
    __syncwarp();

    if (l16 < 4) {
        float lg = dbs[l16];
        #pragma unroll
        for (int i = 0; i < 16; i++) lg += t2s[hid][i] * dws[i * 4 + l16];
        lgs[hid][l16] = lg;
    }
    __syncwarp();

    if (l16 < 4) {
        float l0 = lgs[hid][0], l1 = lgs[hid][1], l2 = lgs[hid][2], l3 = lgs[hid][3];
        float mx = fmaxf(fmaxf(l0, l1), fmaxf(l2, l3));
        float e0 = __expf(l0 - mx), e1 = __expf(l1 - mx);
        float e2 = __expf(l2 - mx), e3 = __expf(l3 - mx);
        float den = e0 + e1 + e2 + e3;
        float mine = (l16 == 0) ? e0 : (l16 == 1) ? e1 : (l16 == 2) ? e2 : e3;
        out[(size_t)n * 4 + l16] = mine / den;
    }
}

// ------------------------------------------------------------------
extern "C" void kernel_launch(void* const* d_in, const int* in_sizes, int n_in,
                              void* d_out, int out_size)
{
    const float* x   = (const float*)d_in[0];
    const int*   ei  = (const int*)  d_in[1];
    int E = in_sizes[1] / 2;
    const int* src = ei;
    const int* dst = ei + E;
    const float* W0  = (const float*)d_in[2];
    const float* as0 = (const float*)d_in[3];
    const float* ad0 = (const float*)d_in[4];
    const float* b0  = (const float*)d_in[5];
    const float* W1  = (const float*)d_in[6];
    const float* as1 = (const float*)d_in[7];
    const float* ad1 = (const float*)d_in[8];
    const float* b1  = (const float*)d_in[9];
    const float* W2  = (const float*)d_in[10];
    const float* as2 = (const float*)d_in[11];
    const float* ad2 = (const float*)d_in[12];
    const float* b2  = (const float*)d_in[13];
    const float* lw1 = (const float*)d_in[14];
    const float* lb1 = (const float*)d_in[15];
    const float* lw2 = (const float*)d_in[16];
    const float* lb2 = (const float*)d_in[17];
    const float* dw  = (const float*)d_in[18];
    const float* db  = (const float*)d_in[19];
    float* out = (float*)d_out;

    const int AGG16_BLOCKS = (NN + 15) / 16;  // half-warp per node
    const int TRF_BLOCKS   = (NN + 31) / 32;  // 4 nodes/warp, 8 warps/block
    const int NT = 256;
    int FB = (E / 4 + NT - 1) / NT + 1;       // fill blocks (4 edges/thread)

    // CSR build
    k_hist<<<FB, NT>>>(dst, E);
    k_scan1<<<SCAN_NB, 256>>>();
    k_scan3<<<SCAN_NB, SCAN_B>>>();
    k_fill_trf0<<<FB + TRF_BLOCKS, NT>>>(src, dst, E, FB, x, W0, as0, ad0);

    // GAT layer 0 aggregate (rank-1 exact) -> g_fa
    k_agg0<<<AGG16_BLOCKS, NT>>>(x, W0, b0);
    // GAT layer 1: transform from g_fa, aggregate -> g_fb
    k_transform<<<TRF_BLOCKS, NT>>>(1, W1, as1, ad1, 1);
    k_aggregate<<<AGG16_BLOCKS, NT>>>(b1, 1);
    // GAT layer 2: transform from g_fb, fused aggregate + MLP -> out
    k_transform<<<TRF_BLOCKS, NT>>>(2, W2, as2, ad2, 2);
    k_agg_mlp<<<AGG16_BLOCKS, NT>>>(b2, 2, lw1, lb1, lw2, lb2, dw, db, out);
}

// round 15
// speedup vs baseline: 1.1303x; 1.0024x over previous
#include <cuda_runtime.h>

#define NN 100000
#define EMAX 1600000
#define SCAN_B 1024
#define SCAN_NB ((NN + SCAN_B - 1) / SCAN_B)   // 98

// ---- scratch (device globals; no runtime allocation allowed) ----
__device__ int      g_deg[NN];          // zero at load; re-zeroed by k_scan3 each launch
__device__ int      g_off[NN + 1];
__device__ int      g_cur[NN];
__device__ int      g_csr[EMAX + NN];   // src node per CSR slot (sorted by dst)
__device__ float    g_h [NN * 64];      // transformed features for current layer
__device__ float    g_fa[NN * 64];      // ping
__device__ float    g_fb[NN * 64];      // pong
__device__ float    g_es[NN * 4];       // per-node source attention logits
__device__ float    g_ed[NN * 4];       // per-node dest attention logits
__device__ unsigned g_gmax[12];         // monotone across replays (same values each run)
__device__ int      g_bsum[SCAN_NB];

__device__ __forceinline__ unsigned fenc(float f) {
    unsigned u = __float_as_uint(f);
    return u ^ ((u & 0x80000000u) ? 0xFFFFFFFFu : 0x80000000u);
}
__device__ __forceinline__ float fdec(unsigned e) {
    unsigned u = e ^ ((e & 0x80000000u) ? 0x80000000u : 0xFFFFFFFFu);
    return __uint_as_float(u);
}
__device__ __forceinline__ float leaky02(float e) {
    return (e > 0.f) ? e : 0.2f * e;
}

// ------------------------------------------------------------------
// CSR construction
// ------------------------------------------------------------------
__global__ void k_hist(const int* __restrict__ dst, int E) {
    int i4 = (blockIdx.x * blockDim.x + threadIdx.x) * 4;
    if (i4 + 4 <= E) {
        int4 d = __ldg((const int4*)(dst + i4));
        atomicAdd(&g_deg[d.x], 1);
        atomicAdd(&g_deg[d.y], 1);
        atomicAdd(&g_deg[d.z], 1);
        atomicAdd(&g_deg[d.w], 1);
    } else {
        for (int i = i4; i < E; i++) atomicAdd(&g_deg[__ldg(dst + i)], 1);
    }
}

__global__ void k_scan1() {
    __shared__ int red[8];
    int b = blockIdx.x, t = threadIdx.x;
    int s = 0;
    #pragma unroll
    for (int j = 0; j < 4; j++) {
        int idx = b * SCAN_B + j * 256 + t;
        if (idx < NN) s += g_deg[idx] + 1;        // +1 self-loop
    }
    #pragma unroll
    for (int o = 16; o >= 1; o >>= 1) s += __shfl_down_sync(0xffffffffu, s, o);
    if ((t & 31) == 0) red[t >> 5] = s;
    __syncthreads();
    if (t == 0) {
        int tot = 0;
        #pragma unroll
        for (int w = 0; w < 8; w++) tot += red[w];
        g_bsum[b] = tot;
    }
}

__global__ void k_scan3() {
    __shared__ int sh[SCAN_B];
    __shared__ int redsum[32];
    __shared__ int s_bo;
    int b = blockIdx.x, t = threadIdx.x;
    {
        int v = (t < SCAN_NB && t < b) ? g_bsum[t] : 0;
        #pragma unroll
        for (int o = 16; o >= 1; o >>= 1) v += __shfl_down_sync(0xffffffffu, v, o);
        if ((t & 31) == 0) redsum[t >> 5] = v;
        __syncthreads();
        if (t == 0) {
            int s = 0;
            #pragma unroll
            for (int w = 0; w < 32; w++) s += redsum[w];
            s_bo = s;
        }
        __syncthreads();
    }
    int bo = s_bo;

    int i = b * SCAN_B + t;
    int v = 0;
    if (i < NN) {
        v = g_deg[i] + 1;       // +1 self-loop
        g_deg[i] = 0;           // reset for next replay
    }
    sh[t] = v;
    __syncthreads();
    for (int o = 1; o < SCAN_B; o <<= 1) {
        int u = (t >= o) ? sh[t - o] : 0;
        __syncthreads();
        sh[t] += u;
        __syncthreads();
    }
    if (i < NN) {
        int ex = sh[t] - v + bo;
        g_off[i] = ex;
        g_csr[ex] = i;          // self-loop first
        g_cur[i] = ex + 1;
    }
    if (b == SCAN_NB - 1 && t == SCAN_B - 1)
        g_off[NN] = bo + sh[SCAN_B - 1];
}

// ------------------------------------------------------------------
// Fused launch: blocks [0, FB) fill CSR edges; blocks [FB, ...) compute
// layer-0 attention logits (h0 never materialized — agg0 is rank-1).
// ------------------------------------------------------------------
__global__ __launch_bounds__(256) void k_fill_trf0(
    const int* __restrict__ src, const int* __restrict__ dst, int E, int FB,
    const float* __restrict__ x,
    const float* __restrict__ Wg,
    const float* __restrict__ avs,
    const float* __restrict__ avd)
{
    if (blockIdx.x < FB) {
        int i4 = (blockIdx.x * blockDim.x + threadIdx.x) * 4;
        if (i4 + 4 <= E) {
            int4 s = __ldg((const int4*)(src + i4));
            int4 d = __ldg((const int4*)(dst + i4));
            g_csr[atomicAdd(&g_cur[d.x], 1)] = s.x;
            g_csr[atomicAdd(&g_cur[d.y], 1)] = s.y;
            g_csr[atomicAdd(&g_cur[d.z], 1)] = s.z;
            g_csr[atomicAdd(&g_cur[d.w], 1)] = s.w;
        } else {
            for (int i = i4; i < E; i++) {
                int s = __ldg(src + i), d = __ldg(dst + i);
                g_csr[atomicAdd(&g_cur[d], 1)] = s;
            }
        }
        return;
    }

    __shared__ float Ws[64];
    __shared__ float As[64], Ad[64];
    __shared__ unsigned bmax[4];
    int t = threadIdx.x;
    if (t < 64) { Ws[t] = Wg[t]; As[t] = avs[t]; Ad[t] = avd[t]; }
    if (t < 4)  bmax[t] = 0u;
    __syncthreads();

    int lane = t & 31;
    int c0   = lane * 2;
    int n0 = (blockIdx.x - FB) * 32 + (t >> 5) * 4;

    #pragma unroll
    for (int r = 0; r < 4; r++) {
        int n = n0 + r;
        if (n >= NN) break;
        float xv = __ldg(x + n);
        float a0 = xv * Ws[c0];
        float a1 = xv * Ws[c0 + 1];
        float ps = a0 * As[c0] + a1 * As[c0 + 1];
        float pd = a0 * Ad[c0] + a1 * Ad[c0 + 1];
        #pragma unroll
        for (int o = 4; o >= 1; o >>= 1) {
            ps += __shfl_down_sync(0xffffffffu, ps, o);
            pd += __shfl_down_sync(0xffffffffu, pd, o);
        }
        if ((lane & 7) == 0) {
            int hd = lane >> 3;
            g_es[n * 4 + hd] = ps;
            g_ed[n * 4 + hd] = pd;
            atomicMax(&bmax[hd], fenc(ps));
        }
    }
    __syncthreads();
    if (t < 4) atomicMax(&g_gmax[t], bmax[t]);
}

// ------------------------------------------------------------------
// Layer-0 aggregate, rank-1 exact factorization, with csr prefetch.
// ------------------------------------------------------------------
__global__ __launch_bounds__(256) void k_agg0(
    const float* __restrict__ x,
    const float* __restrict__ W0,
    const float* __restrict__ b0)
{
    int t    = threadIdx.x;
    int lane = t & 31;
    int l16  = lane & 15;
    int hb   = lane & 16;
    unsigned hmask = 0xFFFFu << hb;
    int n = blockIdx.x * 16 + (t >> 4);
    if (n >= NN) return;

    int hd = l16 >> 2;
    int q0 = l16 * 4;
    int beg = __ldg(&g_off[n]), end = __ldg(&g_off[n + 1]);
    float edv = __ldg(&g_ed[n * 4 + hd]);
    float m = leaky02(fdec(g_gmax[hd]) + edv);

    float s = 0.f, ax = 0.f;
    int rem0 = end - beg;
    int myidx = __ldg(&g_csr[beg + (l16 < rem0 ? l16 : 0)]);
    for (int base = beg; base < end; base += 16) {
        int rem = end - base;
        int cnt = rem < 16 ? rem : 16;
        // prefetch next chunk's indices (overlaps this chunk's gathers)
        int nb = base + 16;
        int nidx = myidx;
        if (nb < end) {
            int nrem = end - nb;
            nidx = __ldg(&g_csr[nb + (l16 < nrem ? l16 : 0)]);
        }
        int j = 0;
        for (; j + 8 <= cnt; j += 8) {
            int sc[8]; float ev[8], xs[8];
            #pragma unroll
            for (int q = 0; q < 8; q++)
                sc[q] = __shfl_sync(hmask, myidx, hb + j + q);
            #pragma unroll
            for (int q = 0; q < 8; q++) {
                ev[q] = __ldg(&g_es[sc[q] * 4 + hd]);
                xs[q] = __ldg(x + sc[q]);
            }
            #pragma unroll
            for (int q = 0; q < 8; q++) {
                float w = __expf(leaky02(ev[q] + edv) - m);
                s  += w;
                ax += w * xs[q];
            }
        }
        if (j + 4 <= cnt) {
            int sc[4]; float ev[4], xs[4];
            #pragma unroll
            for (int q = 0; q < 4; q++)
                sc[q] = __shfl_sync(hmask, myidx, hb + j + q);
            #pragma unroll
            for (int q = 0; q < 4; q++) {
                ev[q] = __ldg(&g_es[sc[q] * 4 + hd]);
                xs[q] = __ldg(x + sc[q]);
            }
            #pragma unroll
            for (int q = 0; q < 4; q++) {
                float w = __expf(leaky02(ev[q] + edv) - m);
                s  += w;
                ax += w * xs[q];
            }
            j += 4;
        }
        for (; j < cnt; j++) {
            int sc = __shfl_sync(hmask, myidx, hb + j);
            float e  = __ldg(&g_es[sc * 4 + hd]);
            float xv = __ldg(x + sc);
            float w = __expf(leaky02(e + edv) - m);
            s  += w;
            ax += w * xv;
        }
        myidx = nidx;
    }
    float val = ax / (s + 1e-16f);
    float4 w4 = __ldg((const float4*)(W0 + q0));
    float4 bv = __ldg((const float4*)(b0 + q0));
    float4 o;
    o.x = val * w4.x + bv.x;
    o.y = val * w4.y + bv.y;
    o.z = val * w4.z + bv.z;
    o.w = val * w4.w + bv.w;
    *(float4*)(g_fa + (size_t)n * 64 + q0) = o;
}

// ------------------------------------------------------------------
// Node transform (Fin=64): 4 nodes per warp, hoisted W smem loads.
// ------------------------------------------------------------------
__global__ __launch_bounds__(256) void k_transform(
    int xin_sel,
    const float* __restrict__ Wg,
    const float* __restrict__ avs,
    const float* __restrict__ avd,
    int layer)
{
    __shared__ float Ws[64 * 64];
    __shared__ float As[64], Ad[64];
    __shared__ unsigned bmax[4];
    const float* xin = (xin_sel == 1) ? g_fa : g_fb;
    int t = threadIdx.x;
    {
        const float4* W4 = (const float4*)Wg;
        float4* Ws4 = (float4*)Ws;
        for (int i = t; i < 64 * 16; i += blockDim.x) Ws4[i] = __ldg(W4 + i);
    }
    if (t < 64) { As[t] = avs[t]; Ad[t] = avd[t]; }
    if (t < 4)  bmax[t] = 0u;
    __syncthreads();

    int lane = t & 31;
    int c0   = lane * 2;
    int n0 = blockIdx.x * 32 + (t >> 5) * 4;
    int nv = NN - n0; if (nv > 4) nv = 4;

    float acc[4][2];
    #pragma unroll
    for (int r = 0; r < 4; r++) { acc[r][0] = 0.f; acc[r][1] = 0.f; }

    const float* x0p = xin + (size_t)n0 * 64;
    #pragma unroll
    for (int k = 0; k < 64; k += 4) {
        float2 w0 = *(const float2*)(Ws + (k + 0) * 64 + c0);
        float2 w1 = *(const float2*)(Ws + (k + 1) * 64 + c0);
        float2 w2 = *(const float2*)(Ws + (k + 2) * 64 + c0);
        float2 w3 = *(const float2*)(Ws + (k + 3) * 64 + c0);
        #pragma unroll
        for (int r = 0; r < 4; r++) {
            if (r < nv) {
                float4 xv = __ldg((const float4*)(x0p + r * 64 + k));
                acc[r][0] += xv.x * w0.x; acc[r][1] += xv.x * w0.y;
                acc[r][0] += xv.y * w1.x; acc[r][1] += xv.y * w1.y;
                acc[r][0] += xv.z * w2.x; acc[r][1] += xv.z * w2.y;
                acc[r][0] += xv.w * w3.x; acc[r][1] += xv.w * w3.y;
            }
        }
    }

    #pragma unroll
    for (int r = 0; r < 4; r++) {
        if (r >= nv) break;
        int n = n0 + r;
        float a0 = acc[r][0], a1 = acc[r][1];
        float2 hv2; hv2.x = a0; hv2.y = a1;
        *(float2*)(g_h + (size_t)n * 64 + c0) = hv2;
        float ps = a0 * As[c0] + a1 * As[c0 + 1];
        float pd = a0 * Ad[c0] + a1 * Ad[c0 + 1];
        #pragma unroll
        for (int o = 4; o >= 1; o >>= 1) {
            ps += __shfl_down_sync(0xffffffffu, ps, o);
            pd += __shfl_down_sync(0xffffffffu, pd, o);
        }
        if ((lane & 7) == 0) {
            int hd = lane >> 3;
            g_es[n * 4 + hd] = ps;
            g_ed[n * 4 + hd] = pd;
            atomicMax(&bmax[hd], fenc(ps));
        }
    }
    __syncthreads();
    if (t < 4) atomicMax(&g_gmax[layer * 4 + t], bmax[t]);
}

// ------------------------------------------------------------------
// Half-warp (16-lane) single-pass softmax aggregation (R9-proven)
// with software-pipelined csr chunk loads.
// ------------------------------------------------------------------
__device__ __forceinline__ float4 agg_node16(
    int n, int l16, int hb, unsigned hmask, int layer,
    const float* __restrict__ bias)
{
    int hd = l16 >> 2;
    int q0 = l16 * 4;
    int beg = __ldg(&g_off[n]), end = __ldg(&g_off[n + 1]);
    float edv = __ldg(&g_ed[n * 4 + hd]);
    float m = leaky02(fdec(g_gmax[layer * 4 + hd]) + edv);

    float s = 0.f;
    float a0 = 0.f, a1 = 0.f, a2 = 0.f, a3 = 0.f;
    int rem0 = end - beg;
    int myidx = __ldg(&g_csr[beg + (l16 < rem0 ? l16 : 0)]);
    for (int base = beg; base < end; base += 16) {
        int rem = end - base;
        int cnt = rem < 16 ? rem : 16;
        // prefetch next chunk's indices (overlaps this chunk's gathers)
        int nb = base + 16;
        int nidx = myidx;
        if (nb < end) {
            int nrem = end - nb;
            nidx = __ldg(&g_csr[nb + (l16 < nrem ? l16 : 0)]);
        }
        int j = 0;
        for (; j + 8 <= cnt; j += 8) {
            int sc[8]; float ev[8]; float4 hv[8];
            #pragma unroll
            for (int q = 0; q < 8; q++)
                sc[q] = __shfl_sync(hmask, myidx, hb + j + q);
            #pragma unroll
            for (int q = 0; q < 8; q++) {
                ev[q] = __ldg(&g_es[sc[q] * 4 + hd]);
                hv[q] = __ldg((const float4*)(g_h + (size_t)sc[q] * 64 + q0));
            }
            #pragma unroll
            for (int q = 0; q < 8; q++) {
                float w = __expf(leaky02(ev[q] + edv) - m);
                s  += w;
                a0 += w * hv[q].x; a1 += w * hv[q].y;
                a2 += w * hv[q].z; a3 += w * hv[q].w;
            }
        }
        if (j + 4 <= cnt) {
            int sc[4]; float ev[4]; float4 hv[4];
            #pragma unroll
            for (int q = 0; q < 4; q++)
                sc[q] = __shfl_sync(hmask, myidx, hb + j + q);
            #pragma unroll
            for (int q = 0; q < 4; q++) {
                ev[q] = __ldg(&g_es[sc[q] * 4 + hd]);
                hv[q] = __ldg((const float4*)(g_h + (size_t)sc[q] * 64 + q0));
            }
            #pragma unroll
            for (int q = 0; q < 4; q++) {
                float w = __expf(leaky02(ev[q] + edv) - m);
                s  += w;
                a0 += w * hv[q].x; a1 += w * hv[q].y;
                a2 += w * hv[q].z; a3 += w * hv[q].w;
            }
            j += 4;
        }
        for (; j < cnt; j++) {
            int sc = __shfl_sync(hmask, myidx, hb + j);
            float  e  = __ldg(&g_es[sc * 4 + hd]);
            float4 hv = __ldg((const float4*)(g_h + (size_t)sc * 64 + q0));
            float w = __expf(leaky02(e + edv) - m);
            s  += w;
            a0 += w * hv.x; a1 += w * hv.y;
            a2 += w * hv.z; a3 += w * hv.w;
        }
        myidx = nidx;
    }
    float inv = 1.f / (s + 1e-16f);
    float4 bv = __ldg((const float4*)(bias + q0));
    float4 o;
    o.x = a0 * inv + bv.x;
    o.y = a1 * inv + bv.y;
    o.z = a2 * inv + bv.z;
    o.w = a3 * inv + bv.w;
    return o;
}

// ------------------------------------------------------------------
// Aggregation layer 1 -> g_fb: half-warp per node
// ------------------------------------------------------------------
__global__ __launch_bounds__(256) void k_aggregate(
    const float* __restrict__ bias, int layer)
{
    int t    = threadIdx.x;
    int lane = t & 31;
    int l16  = lane & 15;
    int hb   = lane & 16;
    unsigned hmask = 0xFFFFu << hb;
    int n = blockIdx.x * 16 + (t >> 4);
    if (n >= NN) return;
    float4 o = agg_node16(n, l16, hb, hmask, layer, bias);
    *(float4*)(g_fb + (size_t)n * 64 + l16 * 4) = o;
}

// ------------------------------------------------------------------
// Layer-2 aggregate fused with MLP + decoder + softmax.
// ------------------------------------------------------------------
__global__ __launch_bounds__(256) void k_agg_mlp(
    const float* __restrict__ bias, int layer,
    const float* __restrict__ lw1, const float* __restrict__ lb1,
    const float* __restrict__ lw2, const float* __restrict__ lb2,
    const float* __restrict__ dw,  const float* __restrict__ db,
    float* __restrict__ out)
{
    __shared__ float W1s[64 * 64];
    __shared__ float W2s[64 * 16];
    __shared__ float b1s[64], b2s[16], dws[64], dbs[4];
    __shared__ float t1s[16][68];
    __shared__ float t2s[16][16];
    __shared__ float lgs[16][4];
    int t = threadIdx.x;
    {
        const float4* W14 = (const float4*)lw1;
        float4* W1s4 = (float4*)W1s;
        for (int i = t; i < 64 * 16; i += blockDim.x) W1s4[i] = __ldg(W14 + i);
        const float4* W24 = (const float4*)lw2;
        float4* W2s4 = (float4*)W2s;
        for (int i = t; i < 16 * 16; i += blockDim.x) W2s4[i] = __ldg(W24 + i);
    }
    if (t < 64) b1s[t] = lb1[t];
    if (t < 16) b2s[t] = lb2[t];
    if (t < 64) dws[t] = dw[t];
    if (t < 4)  dbs[t] = db[t];
    __syncthreads();

    int lane = t & 31;
    int l16  = lane & 15;
    int hb   = lane & 16;
    unsigned hmask = 0xFFFFu << hb;
    int hid  = t >> 4;
    int q0   = l16 * 4;
    int n = blockIdx.x * 16 + hid;
    if (n >= NN) return;

    float4 xr = agg_node16(n, l16, hb, hmask, layer, bias);
    *(float4*)(&t1s[hid][q0]) = xr;
    __syncwarp();

    float a0 = b1s[q0], a1 = b1s[q0 + 1], a2 = b1s[q0 + 2], a3 = b1s[q0 + 3];
    #pragma unroll
    for (int k = 0; k < 64; k++) {
        float xv = t1s[hid][k];
        float4 wv = *(const float4*)(W1s + k * 64 + q0);
        a0 += xv * wv.x; a1 += xv * wv.y;
        a2 += xv * wv.z; a3 += xv * wv.w;
    }
    a0 = a0 > 0.f ? a0 : 0.f;
    a1 = a1 > 0.f ? a1 : 0.f;
    a2 = a2 > 0.f ? a2 : 0.f;
    a3 = a3 > 0.f ? a3 : 0.f;
    __syncwarp();
    t1s[hid][q0]     = a0;
    t1s[hid][q0 + 1] = a1;
    t1s[hid][q0 + 2] = a2;
    t1s[hid][q0 + 3] = a3;
    __syncwarp();

    {
        float acc = b2s[l16];
        #pragma unroll
        for (int k = 0; k < 64; k++) acc += t1s[hid][k] * W2s[k * 16 + l16];
        t2s[hid][l16] = acc;
    }
    __syncwarp();

    if (l16 < 4) {
        float lg = dbs[l16];
        #pragma unroll
        for (int i = 0; i < 16; i++) lg += t2s[hid][i] * dws[i * 4 + l16];
        lgs[hid][l16] = lg;
    }
    __syncwarp();

    if (l16 < 4) {
        float l0 = lgs[hid][0], l1 = lgs[hid][1], l2 = lgs[hid][2], l3 = lgs[hid][3];
        float mx = fmaxf(fmaxf(l0, l1), fmaxf(l2, l3));
        float e0 = __expf(l0 - mx), e1 = __expf(l1 - mx);
        float e2 = __expf(l2 - mx), e3 = __expf(l3 - mx);
        float den = e0 + e1 + e2 + e3;
        float mine = (l16 == 0) ? e0 : (l16 == 1) ? e1 : (l16 == 2) ? e2 : e3;
        out[(size_t)n * 4 + l16] = mine / den;
    }
}

// ------------------------------------------------------------------
extern "C" void kernel_launch(void* const* d_in, const int* in_sizes, int n_in,
                              void* d_out, int out_size)
{
    const float* x   = (const float*)d_in[0];
    const int*   ei  = (const int*)  d_in[1];
    int E = in_sizes[1] / 2;
    const int* src = ei;
    const int* dst = ei + E;
    const float* W0  = (const float*)d_in[2];
    const float* as0 = (const float*)d_in[3];
    const float* ad0 = (const float*)d_in[4];
    const float* b0  = (const float*)d_in[5];
    const float* W1  = (const float*)d_in[6];
    const float* as1 = (const float*)d_in[7];
    const float* ad1 = (const float*)d_in[8];
    const float* b1  = (const float*)d_in[9];
    const float* W2  = (const float*)d_in[10];
    const float* as2 = (const float*)d_in[11];
    const float* ad2 = (const float*)d_in[12];
    const float* b2  = (const float*)d_in[13];
    const float* lw1 = (const float*)d_in[14];
    const float* lb1 = (const float*)d_in[15];
    const float* lw2 = (const float*)d_in[16];
    const float* lb2 = (const float*)d_in[17];
    const float* dw  = (const float*)d_in[18];
    const float* db  = (const float*)d_in[19];
    float* out = (float*)d_out;

    const int AGG16_BLOCKS = (NN + 15) / 16;
    const int TRF_BLOCKS   = (NN + 31) / 32;
    const int NT = 256;
    int FB = (E / 4 + NT - 1) / NT + 1;

    // CSR build
    k_hist<<<FB, NT>>>(dst, E);
    k_scan1<<<SCAN_NB, 256>>>();
    k_scan3<<<SCAN_NB, SCAN_B>>>();
    k_fill_trf0<<<FB + TRF_BLOCKS, NT>>>(src, dst, E, FB, x, W0, as0, ad0);

    // GAT layer 0 aggregate (rank-1 exact) -> g_fa
    k_agg0<<<AGG16_BLOCKS, NT>>>(x, W0, b0);
    // GAT layer 1: transform from g_fa, aggregate -> g_fb
    k_transform<<<TRF_BLOCKS, NT>>>(1, W1, as1, ad1, 1);
    k_aggregate<<<AGG16_BLOCKS, NT>>>(b1, 1);
    // GAT layer 2: transform from g_fb, fused aggregate + MLP -> out
    k_transform<<<TRF_BLOCKS, NT>>>(2, W2, as2, ad2, 2);
    k_agg_mlp<<<AGG16_BLOCKS, NT>>>(b2, 2, lw1, lb1, lw2, lb2, dw, db, out);
}

// round 16
// speedup vs baseline: 1.1663x; 1.0319x over previous
#include <cuda_runtime.h>
#include <cuda_fp16.h>

#define NN 100000
#define EMAX 1600000
#define SCAN_B 1024
#define SCAN_NB ((NN + SCAN_B - 1) / SCAN_B)   // 98

// ---- scratch (device globals; no runtime allocation allowed) ----
__device__ int      g_deg[NN];          // zero at load; re-zeroed by k_scan3 each launch
__device__ int      g_off[NN + 1];
__device__ int      g_cur[NN];
__device__ int      g_csr[EMAX + NN];   // src node per CSR slot (sorted by dst)
__device__ __half   g_h [NN * 64];      // transformed features (fp16 message payload)
__device__ float    g_fa[NN * 64];      // ping (aggregate outputs, fp32)
__device__ float    g_fb[NN * 64];      // pong
__device__ float    g_es[NN * 4];       // per-node source attention logits (fp32, exact)
__device__ float    g_ed[NN * 4];       // per-node dest attention logits
__device__ unsigned g_gmax[12];         // monotone across replays (same values each run)
__device__ int      g_bsum[SCAN_NB];

__device__ __forceinline__ unsigned fenc(float f) {
    unsigned u = __float_as_uint(f);
    return u ^ ((u & 0x80000000u) ? 0xFFFFFFFFu : 0x80000000u);
}
__device__ __forceinline__ float fdec(unsigned e) {
    unsigned u = e ^ ((e & 0x80000000u) ? 0x80000000u : 0xFFFFFFFFu);
    return __uint_as_float(u);
}
__device__ __forceinline__ float leaky02(float e) {
    return (e > 0.f) ? e : 0.2f * e;
}
// load 4 fp16 channels (8B) and widen to float4
__device__ __forceinline__ float4 ldh4(const __half* p) {
    float2 raw = __ldg((const float2*)p);
    __half2 h0 = *(__half2*)&raw.x;
    __half2 h1 = *(__half2*)&raw.y;
    float2 f0 = __half22float2(h0);
    float2 f1 = __half22float2(h1);
    float4 r; r.x = f0.x; r.y = f0.y; r.z = f1.x; r.w = f1.y;
    return r;
}

// ------------------------------------------------------------------
// CSR construction
// ------------------------------------------------------------------
__global__ void k_hist(const int* __restrict__ dst, int E) {
    int i4 = (blockIdx.x * blockDim.x + threadIdx.x) * 4;
    if (i4 + 4 <= E) {
        int4 d = __ldg((const int4*)(dst + i4));
        atomicAdd(&g_deg[d.x], 1);
        atomicAdd(&g_deg[d.y], 1);
        atomicAdd(&g_deg[d.z], 1);
        atomicAdd(&g_deg[d.w], 1);
    } else {
        for (int i = i4; i < E; i++) atomicAdd(&g_deg[__ldg(dst + i)], 1);
    }
}

__global__ void k_scan1() {
    __shared__ int red[8];
    int b = blockIdx.x, t = threadIdx.x;
    int s = 0;
    #pragma unroll
    for (int j = 0; j < 4; j++) {
        int idx = b * SCAN_B + j * 256 + t;
        if (idx < NN) s += g_deg[idx] + 1;        // +1 self-loop
    }
    #pragma unroll
    for (int o = 16; o >= 1; o >>= 1) s += __shfl_down_sync(0xffffffffu, s, o);
    if ((t & 31) == 0) red[t >> 5] = s;
    __syncthreads();
    if (t == 0) {
        int tot = 0;
        #pragma unroll
        for (int w = 0; w < 8; w++) tot += red[w];
        g_bsum[b] = tot;
    }
}

__global__ void k_scan3() {
    __shared__ int sh[SCAN_B];
    __shared__ int redsum[32];
    __shared__ int s_bo;
    int b = blockIdx.x, t = threadIdx.x;
    {
        int v = (t < SCAN_NB && t < b) ? g_bsum[t] : 0;
        #pragma unroll
        for (int o = 16; o >= 1; o >>= 1) v += __shfl_down_sync(0xffffffffu, v, o);
        if ((t & 31) == 0) redsum[t >> 5] = v;
        __syncthreads();
        if (t == 0) {
            int s = 0;
            #pragma unroll
            for (int w = 0; w < 32; w++) s += redsum[w];
            s_bo = s;
        }
        __syncthreads();
    }
    int bo = s_bo;

    int i = b * SCAN_B + t;
    int v = 0;
    if (i < NN) {
        v = g_deg[i] + 1;       // +1 self-loop
        g_deg[i] = 0;           // reset for next replay
    }
    sh[t] = v;
    __syncthreads();
    for (int o = 1; o < SCAN_B; o <<= 1) {
        int u = (t >= o) ? sh[t - o] : 0;
        __syncthreads();
        sh[t] += u;
        __syncthreads();
    }
    if (i < NN) {
        int ex = sh[t] - v + bo;
        g_off[i] = ex;
        g_csr[ex] = i;          // self-loop first
        g_cur[i] = ex + 1;
    }
    if (b == SCAN_NB - 1 && t == SCAN_B - 1)
        g_off[NN] = bo + sh[SCAN_B - 1];
}

// ------------------------------------------------------------------
// Fused launch: blocks [0, FB) fill CSR edges; blocks [FB, ...) compute
// layer-0 attention logits (h0 never materialized — agg0 is rank-1).
// ------------------------------------------------------------------
__global__ __launch_bounds__(256) void k_fill_trf0(
    const int* __restrict__ src, const int* __restrict__ dst, int E, int FB,
    const float* __restrict__ x,
    const float* __restrict__ Wg,
    const float* __restrict__ avs,
    const float* __restrict__ avd)
{
    if (blockIdx.x < FB) {
        int i4 = (blockIdx.x * blockDim.x + threadIdx.x) * 4;
        if (i4 + 4 <= E) {
            int4 s = __ldg((const int4*)(src + i4));
            int4 d = __ldg((const int4*)(dst + i4));
            g_csr[atomicAdd(&g_cur[d.x], 1)] = s.x;
            g_csr[atomicAdd(&g_cur[d.y], 1)] = s.y;
            g_csr[atomicAdd(&g_cur[d.z], 1)] = s.z;
            g_csr[atomicAdd(&g_cur[d.w], 1)] = s.w;
        } else {
            for (int i = i4; i < E; i++) {
                int s = __ldg(src + i), d = __ldg(dst + i);
                g_csr[atomicAdd(&g_cur[d], 1)] = s;
            }
        }
        return;
    }

    __shared__ float Ws[64];
    __shared__ float As[64], Ad[64];
    __shared__ unsigned bmax[4];
    int t = threadIdx.x;
    if (t < 64) { Ws[t] = Wg[t]; As[t] = avs[t]; Ad[t] = avd[t]; }
    if (t < 4)  bmax[t] = 0u;
    __syncthreads();

    int lane = t & 31;
    int c0   = lane * 2;
    int n0 = (blockIdx.x - FB) * 32 + (t >> 5) * 4;

    #pragma unroll
    for (int r = 0; r < 4; r++) {
        int n = n0 + r;
        if (n >= NN) break;
        float xv = __ldg(x + n);
        float a0 = xv * Ws[c0];
        float a1 = xv * Ws[c0 + 1];
        float ps = a0 * As[c0] + a1 * As[c0 + 1];
        float pd = a0 * Ad[c0] + a1 * Ad[c0 + 1];
        #pragma unroll
        for (int o = 4; o >= 1; o >>= 1) {
            ps += __shfl_down_sync(0xffffffffu, ps, o);
            pd += __shfl_down_sync(0xffffffffu, pd, o);
        }
        if ((lane & 7) == 0) {
            int hd = lane >> 3;
            g_es[n * 4 + hd] = ps;
            g_ed[n * 4 + hd] = pd;
            atomicMax(&bmax[hd], fenc(ps));
        }
    }
    __syncthreads();
    if (t < 4) atomicMax(&g_gmax[t], bmax[t]);
}

// ------------------------------------------------------------------
// Layer-0 aggregate, rank-1 exact factorization, csr prefetch.
// ------------------------------------------------------------------
__global__ __launch_bounds__(256) void k_agg0(
    const float* __restrict__ x,
    const float* __restrict__ W0,
    const float* __restrict__ b0)
{
    int t    = threadIdx.x;
    int lane = t & 31;
    int l16  = lane & 15;
    int hb   = lane & 16;
    unsigned hmask = 0xFFFFu << hb;
    int n = blockIdx.x * 16 + (t >> 4);
    if (n >= NN) return;

    int hd = l16 >> 2;
    int q0 = l16 * 4;
    int beg = __ldg(&g_off[n]), end = __ldg(&g_off[n + 1]);
    float edv = __ldg(&g_ed[n * 4 + hd]);
    float m = leaky02(fdec(g_gmax[hd]) + edv);

    float s = 0.f, ax = 0.f;
    int rem0 = end - beg;
    int myidx = __ldg(&g_csr[beg + (l16 < rem0 ? l16 : 0)]);
    for (int base = beg; base < end; base += 16) {
        int rem = end - base;
        int cnt = rem < 16 ? rem : 16;
        int nb = base + 16;
        int nidx = myidx;
        if (nb < end) {
            int nrem = end - nb;
            nidx = __ldg(&g_csr[nb + (l16 < nrem ? l16 : 0)]);
        }
        int j = 0;
        for (; j + 8 <= cnt; j += 8) {
            int sc[8]; float ev[8], xs[8];
            #pragma unroll
            for (int q = 0; q < 8; q++)
                sc[q] = __shfl_sync(hmask, myidx, hb + j + q);
            #pragma unroll
            for (int q = 0; q < 8; q++) {
                ev[q] = __ldg(&g_es[sc[q] * 4 + hd]);
                xs[q] = __ldg(x + sc[q]);
            }
            #pragma unroll
            for (int q = 0; q < 8; q++) {
                float w = __expf(leaky02(ev[q] + edv) - m);
                s  += w;
                ax += w * xs[q];
            }
        }
        if (j + 4 <= cnt) {
            int sc[4]; float ev[4], xs[4];
            #pragma unroll
            for (int q = 0; q < 4; q++)
                sc[q] = __shfl_sync(hmask, myidx, hb + j + q);
            #pragma unroll
            for (int q = 0; q < 4; q++) {
                ev[q] = __ldg(&g_es[sc[q] * 4 + hd]);
                xs[q] = __ldg(x + sc[q]);
            }
            #pragma unroll
            for (int q = 0; q < 4; q++) {
                float w = __expf(leaky02(ev[q] + edv) - m);
                s  += w;
                ax += w * xs[q];
            }
            j += 4;
        }
        for (; j < cnt; j++) {
            int sc = __shfl_sync(hmask, myidx, hb + j);
            float e  = __ldg(&g_es[sc * 4 + hd]);
            float xv = __ldg(x + sc);
            float w = __expf(leaky02(e + edv) - m);
            s  += w;
            ax += w * xv;
        }
        myidx = nidx;
    }
    float val = ax / (s + 1e-16f);
    float4 w4 = __ldg((const float4*)(W0 + q0));
    float4 bv = __ldg((const float4*)(b0 + q0));
    float4 o;
    o.x = val * w4.x + bv.x;
    o.y = val * w4.y + bv.y;
    o.z = val * w4.z + bv.z;
    o.w = val * w4.w + bv.w;
    *(float4*)(g_fa + (size_t)n * 64 + q0) = o;
}

// ------------------------------------------------------------------
// Node transform (Fin=64): 4 nodes per warp, hoisted W smem loads.
// Writes h as fp16 (message payload); es/ed computed from fp32 values.
// ------------------------------------------------------------------
__global__ __launch_bounds__(256) void k_transform(
    int xin_sel,
    const float* __restrict__ Wg,
    const float* __restrict__ avs,
    const float* __restrict__ avd,
    int layer)
{
    __shared__ float Ws[64 * 64];
    __shared__ float As[64], Ad[64];
    __shared__ unsigned bmax[4];
    const float* xin = (xin_sel == 1) ? g_fa : g_fb;
    int t = threadIdx.x;
    {
        const float4* W4 = (const float4*)Wg;
        float4* Ws4 = (float4*)Ws;
        for (int i = t; i < 64 * 16; i += blockDim.x) Ws4[i] = __ldg(W4 + i);
    }
    if (t < 64) { As[t] = avs[t]; Ad[t] = avd[t]; }
    if (t < 4)  bmax[t] = 0u;
    __syncthreads();

    int lane = t & 31;
    int c0   = lane * 2;
    int n0 = blockIdx.x * 32 + (t >> 5) * 4;
    int nv = NN - n0; if (nv > 4) nv = 4;

    float acc[4][2];
    #pragma unroll
    for (int r = 0; r < 4; r++) { acc[r][0] = 0.f; acc[r][1] = 0.f; }

    const float* x0p = xin + (size_t)n0 * 64;
    #pragma unroll
    for (int k = 0; k < 64; k += 4) {
        float2 w0 = *(const float2*)(Ws + (k + 0) * 64 + c0);
        float2 w1 = *(const float2*)(Ws + (k + 1) * 64 + c0);
        float2 w2 = *(const float2*)(Ws + (k + 2) * 64 + c0);
        float2 w3 = *(const float2*)(Ws + (k + 3) * 64 + c0);
        #pragma unroll
        for (int r = 0; r < 4; r++) {
            if (r < nv) {
                float4 xv = __ldg((const float4*)(x0p + r * 64 + k));
                acc[r][0] += xv.x * w0.x; acc[r][1] += xv.x * w0.y;
                acc[r][0] += xv.y * w1.x; acc[r][1] += xv.y * w1.y;
                acc[r][0] += xv.z * w2.x; acc[r][1] += xv.z * w2.y;
                acc[r][0] += xv.w * w3.x; acc[r][1] += xv.w * w3.y;
            }
        }
    }

    #pragma unroll
    for (int r = 0; r < 4; r++) {
        if (r >= nv) break;
        int n = n0 + r;
        float a0 = acc[r][0], a1 = acc[r][1];
        *(__half2*)(g_h + (size_t)n * 64 + c0) = __floats2half2_rn(a0, a1);
        float ps = a0 * As[c0] + a1 * As[c0 + 1];
        float pd = a0 * Ad[c0] + a1 * Ad[c0 + 1];
        #pragma unroll
        for (int o = 4; o >= 1; o >>= 1) {
            ps += __shfl_down_sync(0xffffffffu, ps, o);
            pd += __shfl_down_sync(0xffffffffu, pd, o);
        }
        if ((lane & 7) == 0) {
            int hd = lane >> 3;
            g_es[n * 4 + hd] = ps;
            g_ed[n * 4 + hd] = pd;
            atomicMax(&bmax[hd], fenc(ps));
        }
    }
    __syncthreads();
    if (t < 4) atomicMax(&g_gmax[layer * 4 + t], bmax[t]);
}

// ------------------------------------------------------------------
// Half-warp single-pass softmax aggregation; fp16 h gather (128B/row).
// ------------------------------------------------------------------
__device__ __forceinline__ float4 agg_node16(
    int n, int l16, int hb, unsigned hmask, int layer,
    const float* __restrict__ bias)
{
    int hd = l16 >> 2;
    int q0 = l16 * 4;
    int beg = __ldg(&g_off[n]), end = __ldg(&g_off[n + 1]);
    float edv = __ldg(&g_ed[n * 4 + hd]);
    float m = leaky02(fdec(g_gmax[layer * 4 + hd]) + edv);

    float s = 0.f;
    float a0 = 0.f, a1 = 0.f, a2 = 0.f, a3 = 0.f;
    int rem0 = end - beg;
    int myidx = __ldg(&g_csr[beg + (l16 < rem0 ? l16 : 0)]);
    for (int base = beg; base < end; base += 16) {
        int rem = end - base;
        int cnt = rem < 16 ? rem : 16;
        int nb = base + 16;
        int nidx = myidx;
        if (nb < end) {
            int nrem = end - nb;
            nidx = __ldg(&g_csr[nb + (l16 < nrem ? l16 : 0)]);
        }
        int j = 0;
        for (; j + 8 <= cnt; j += 8) {
            int sc[8]; float ev[8]; float4 hv[8];
            #pragma unroll
            for (int q = 0; q < 8; q++)
                sc[q] = __shfl_sync(hmask, myidx, hb + j + q);
            #pragma unroll
            for (int q = 0; q < 8; q++) {
                ev[q] = __ldg(&g_es[sc[q] * 4 + hd]);
                hv[q] = ldh4(g_h + (size_t)sc[q] * 64 + q0);
            }
            #pragma unroll
            for (int q = 0; q < 8; q++) {
                float w = __expf(leaky02(ev[q] + edv) - m);
                s  += w;
                a0 += w * hv[q].x; a1 += w * hv[q].y;
                a2 += w * hv[q].z; a3 += w * hv[q].w;
            }
        }
        if (j + 4 <= cnt) {
            int sc[4]; float ev[4]; float4 hv[4];
            #pragma unroll
            for (int q = 0; q < 4; q++)
                sc[q] = __shfl_sync(hmask, myidx, hb + j + q);
            #pragma unroll
            for (int q = 0; q < 4; q++) {
                ev[q] = __ldg(&g_es[sc[q] * 4 + hd]);
                hv[q] = ldh4(g_h + (size_t)sc[q] * 64 + q0);
            }
            #pragma unroll
            for (int q = 0; q < 4; q++) {
                float w = __expf(leaky02(ev[q] + edv) - m);
                s  += w;
                a0 += w * hv[q].x; a1 += w * hv[q].y;
                a2 += w * hv[q].z; a3 += w * hv[q].w;
            }
            j += 4;
        }
        for (; j < cnt; j++) {
            int sc = __shfl_sync(hmask, myidx, hb + j);
            float  e  = __ldg(&g_es[sc * 4 + hd]);
            float4 hv = ldh4(g_h + (size_t)sc * 64 + q0);
            float w = __expf(leaky02(e + edv) - m);
            s  += w;
            a0 += w * hv.x; a1 += w * hv.y;
            a2 += w * hv.z; a3 += w * hv.w;
        }
        myidx = nidx;
    }
    float inv = 1.f / (s + 1e-16f);
    float4 bv = __ldg((const float4*)(bias + q0));
    float4 o;
    o.x = a0 * inv + bv.x;
    o.y = a1 * inv + bv.y;
    o.z = a2 * inv + bv.z;
    o.w = a3 * inv + bv.w;
    return o;
}

// ------------------------------------------------------------------
// Aggregation layer 1 -> g_fb: half-warp per node
// ------------------------------------------------------------------
__global__ __launch_bounds__(256) void k_aggregate(
    const float* __restrict__ bias, int layer)
{
    int t    = threadIdx.x;
    int lane = t & 31;
    int l16  = lane & 15;
    int hb   = lane & 16;
    unsigned hmask = 0xFFFFu << hb;
    int n = blockIdx.x * 16 + (t >> 4);
    if (n >= NN) return;
    float4 o = agg_node16(n, l16, hb, hmask, layer, bias);
    *(float4*)(g_fb + (size_t)n * 64 + l16 * 4) = o;
}

// ------------------------------------------------------------------
// Layer-2 aggregate fused with MLP + decoder + softmax.
// ------------------------------------------------------------------
__global__ __launch_bounds__(256) void k_agg_mlp(
    const float* __restrict__ bias, int layer,
    const float* __restrict__ lw1, const float* __restrict__ lb1,
    const float* __restrict__ lw2, const float* __restrict__ lb2,
    const float* __restrict__ dw,  const float* __restrict__ db,
    float* __restrict__ out)
{
    __shared__ float W1s[64 * 64];
    __shared__ float W2s[64 * 16];
    __shared__ float b1s[64], b2s[16], dws[64], dbs[4];
    __shared__ float t1s[16][68];
    __shared__ float t2s[16][16];
    __shared__ float lgs[16][4];
    int t = threadIdx.x;
    {
        const float4* W14 = (const float4*)lw1;
        float4* W1s4 = (float4*)W1s;
        for (int i = t; i < 64 * 16; i += blockDim.x) W1s4[i] = __ldg(W14 + i);
        const float4* W24 = (const float4*)lw2;
        float4* W2s4 = (float4*)W2s;
        for (int i = t; i < 16 * 16; i += blockDim.x) W2s4[i] = __ldg(W24 + i);
    }
    if (t < 64) b1s[t] = lb1[t];
    if (t < 16) b2s[t] = lb2[t];
    if (t < 64) dws[t] = dw[t];
    if (t < 4)  dbs[t] = db[t];
    __syncthreads();

    int lane = t & 31;
    int l16  = lane & 15;
    int hb   = lane & 16;
    unsigned hmask = 0xFFFFu << hb;
    int hid  = t >> 4;
    int q0   = l16 * 4;
    int n = blockIdx.x * 16 + hid;
    if (n >= NN) return;

    float4 xr = agg_node16(n, l16, hb, hmask, layer, bias);
    *(float4*)(&t1s[hid][q0]) = xr;
    __syncwarp();

    float a0 = b1s[q0], a1 = b1s[q0 + 1], a2 = b1s[q0 + 2], a3 = b1s[q0 + 3];
    #pragma unroll
    for (int k = 0; k < 64; k++) {
        float xv = t1s[hid][k];
        float4 wv = *(const float4*)(W1s + k * 64 + q0);
        a0 += xv * wv.x; a1 += xv * wv.y;
        a2 += xv * wv.z; a3 += xv * wv.w;
    }
    a0 = a0 > 0.f ? a0 : 0.f;
    a1 = a1 > 0.f ? a1 : 0.f;
    a2 = a2 > 0.f ? a2 : 0.f;
    a3 = a3 > 0.f ? a3 : 0.f;
    __syncwarp();
    t1s[hid][q0]     = a0;
    t1s[hid][q0 + 1] = a1;
    t1s[hid][q0 + 2] = a2;
    t1s[hid][q0 + 3] = a3;
    __syncwarp();

    {
        float acc = b2s[l16];
        #pragma unroll
        for (int k = 0; k < 64; k++) acc += t1s[hid][k] * W2s[k * 16 + l16];
        t2s[hid][l16] = acc;
    }
    __syncwarp();

    if (l16 < 4) {
        float lg = dbs[l16];
        #pragma unroll
        for (int i = 0; i < 16; i++) lg += t2s[hid][i] * dws[i * 4 + l16];
        lgs[hid][l16] = lg;
    }
    __syncwarp();

    if (l16 < 4) {
        float l0 = lgs[hid][0], l1 = lgs[hid][1], l2 = lgs[hid][2], l3 = lgs[hid][3];
        float mx = fmaxf(fmaxf(l0, l1), fmaxf(l2, l3));
        float e0 = __expf(l0 - mx), e1 = __expf(l1 - mx);
        float e2 = __expf(l2 - mx), e3 = __expf(l3 - mx);
        float den = e0 + e1 + e2 + e3;
        float mine = (l16 == 0) ? e0 : (l16 == 1) ? e1 : (l16 == 2) ? e2 : e3;
        out[(size_t)n * 4 + l16] = mine / den;
    }
}

// ------------------------------------------------------------------
extern "C" void kernel_launch(void* const* d_in, const int* in_sizes, int n_in,
                              void* d_out, int out_size)
{
    const float* x   = (const float*)d_in[0];
    const int*   ei  = (const int*)  d_in[1];
    int E = in_sizes[1] / 2;
    const int* src = ei;
    const int* dst = ei + E;
    const float* W0  = (const float*)d_in[2];
    const float* as0 = (const float*)d_in[3];
    const float* ad0 = (const float*)d_in[4];
    const float* b0  = (const float*)d_in[5];
    const float* W1  = (const float*)d_in[6];
    const float* as1 = (const float*)d_in[7];
    const float* ad1 = (const float*)d_in[8];
    const float* b1  = (const float*)d_in[9];
    const float* W2  = (const float*)d_in[10];
    const float* as2 = (const float*)d_in[11];
    const float* ad2 = (const float*)d_in[12];
    const float* b2  = (const float*)d_in[13];
    const float* lw1 = (const float*)d_in[14];
    const float* lb1 = (const float*)d_in[15];
    const float* lw2 = (const float*)d_in[16];
    const float* lb2 = (const float*)d_in[17];
    const float* dw  = (const float*)d_in[18];
    const float* db  = (const float*)d_in[19];
    float* out = (float*)d_out;

    const int AGG16_BLOCKS = (NN + 15) / 16;
    const int TRF_BLOCKS   = (NN + 31) / 32;
    const int NT = 256;
    int FB = (E / 4 + NT - 1) / NT + 1;

    // CSR build
    k_hist<<<FB, NT>>>(dst, E);
    k_scan1<<<SCAN_NB, 256>>>();
    k_scan3<<<SCAN_NB, SCAN_B>>>();
    k_fill_trf0<<<FB + TRF_BLOCKS, NT>>>(src, dst, E, FB, x, W0, as0, ad0);

    // GAT layer 0 aggregate (rank-1 exact) -> g_fa
    k_agg0<<<AGG16_BLOCKS, NT>>>(x, W0, b0);
    // GAT layer 1: transform from g_fa, aggregate -> g_fb
    k_transform<<<TRF_BLOCKS, NT>>>(1, W1, as1, ad1, 1);
    k_aggregate<<<AGG16_BLOCKS, NT>>>(b1, 1);
    // GAT layer 2: transform from g_fb, fused aggregate + MLP -> out
    k_transform<<<TRF_BLOCKS, NT>>>(2, W2, as2, ad2, 2);
    k_agg_mlp<<<AGG16_BLOCKS, NT>>>(b2, 2, lw1, lb1, lw2, lb2, dw, db, out);
}

// round 17
// speedup vs baseline: 1.1927x; 1.0226x over previous
#include <cuda_runtime.h>
#include <cuda_fp16.h>

#define NN 100000
#define EMAX 1600000
#define SCAN_B 1024
#define SCAN_NB ((NN + SCAN_B - 1) / SCAN_B)   // 98

// ---- scratch (device globals; no runtime allocation allowed) ----
__device__ int      g_deg[NN];          // zero at load; re-zeroed by k_scan3 each launch
__device__ int      g_off[NN + 1];
__device__ int      g_cur[NN];
__device__ int      g_csr[EMAX + NN];   // src node per CSR slot (sorted by dst)
__device__ __half   g_h [NN * 64];      // transformed features (fp16 message payload)
__device__ __half   g_fa[NN * 64];      // ping (aggregate outputs, fp16)
__device__ __half   g_fb[NN * 64];      // pong
__device__ float    g_es[NN * 4];       // per-node source attention logits (fp32, exact)
__device__ float    g_ed[NN * 4];       // per-node dest attention logits
__device__ unsigned g_gmax[12];         // monotone across replays (same values each run)
__device__ int      g_bsum[SCAN_NB];

__device__ __forceinline__ unsigned fenc(float f) {
    unsigned u = __float_as_uint(f);
    return u ^ ((u & 0x80000000u) ? 0xFFFFFFFFu : 0x80000000u);
}
__device__ __forceinline__ float fdec(unsigned e) {
    unsigned u = e ^ ((e & 0x80000000u) ? 0x80000000u : 0xFFFFFFFFu);
    return __uint_as_float(u);
}
__device__ __forceinline__ float leaky02(float e) {
    return (e > 0.f) ? e : 0.2f * e;
}
// load 4 fp16 channels (8B) and widen to float4
__device__ __forceinline__ float4 ldh4(const __half* p) {
    float2 raw = __ldg((const float2*)p);
    __half2 h0 = *(__half2*)&raw.x;
    __half2 h1 = *(__half2*)&raw.y;
    float2 f0 = __half22float2(h0);
    float2 f1 = __half22float2(h1);
    float4 r; r.x = f0.x; r.y = f0.y; r.z = f1.x; r.w = f1.y;
    return r;
}
// store float4 as 4 fp16 (one 8B store)
__device__ __forceinline__ void sth4(__half* p, float4 v) {
    __half2 h0 = __floats2half2_rn(v.x, v.y);
    __half2 h1 = __floats2half2_rn(v.z, v.w);
    float2 raw;
    raw.x = *(float*)&h0;
    raw.y = *(float*)&h1;
    *(float2*)p = raw;
}

// ------------------------------------------------------------------
// CSR construction
// ------------------------------------------------------------------
__global__ void k_hist(const int* __restrict__ dst, int E) {
    int i4 = (blockIdx.x * blockDim.x + threadIdx.x) * 4;
    if (i4 + 4 <= E) {
        int4 d = __ldg((const int4*)(dst + i4));
        atomicAdd(&g_deg[d.x], 1);
        atomicAdd(&g_deg[d.y], 1);
        atomicAdd(&g_deg[d.z], 1);
        atomicAdd(&g_deg[d.w], 1);
    } else {
        for (int i = i4; i < E; i++) atomicAdd(&g_deg[__ldg(dst + i)], 1);
    }
}

__global__ void k_scan1() {
    __shared__ int red[8];
    int b = blockIdx.x, t = threadIdx.x;
    int s = 0;
    #pragma unroll
    for (int j = 0; j < 4; j++) {
        int idx = b * SCAN_B + j * 256 + t;
        if (idx < NN) s += g_deg[idx] + 1;        // +1 self-loop
    }
    #pragma unroll
    for (int o = 16; o >= 1; o >>= 1) s += __shfl_down_sync(0xffffffffu, s, o);
    if ((t & 31) == 0) red[t >> 5] = s;
    __syncthreads();
    if (t == 0) {
        int tot = 0;
        #pragma unroll
        for (int w = 0; w < 8; w++) tot += red[w];
        g_bsum[b] = tot;
    }
}

__global__ void k_scan3() {
    __shared__ int sh[SCAN_B];
    __shared__ int redsum[32];
    __shared__ int s_bo;
    int b = blockIdx.x, t = threadIdx.x;
    {
        int v = (t < SCAN_NB && t < b) ? g_bsum[t] : 0;
        #pragma unroll
        for (int o = 16; o >= 1; o >>= 1) v += __shfl_down_sync(0xffffffffu, v, o);
        if ((t & 31) == 0) redsum[t >> 5] = v;
        __syncthreads();
        if (t == 0) {
            int s = 0;
            #pragma unroll
            for (int w = 0; w < 32; w++) s += redsum[w];
            s_bo = s;
        }
        __syncthreads();
    }
    int bo = s_bo;

    int i = b * SCAN_B + t;
    int v = 0;
    if (i < NN) {
        v = g_deg[i] + 1;       // +1 self-loop
        g_deg[i] = 0;           // reset for next replay
    }
    sh[t] = v;
    __syncthreads();
    for (int o = 1; o < SCAN_B; o <<= 1) {
        int u = (t >= o) ? sh[t - o] : 0;
        __syncthreads();
        sh[t] += u;
        __syncthreads();
    }
    if (i < NN) {
        int ex = sh[t] - v + bo;
        g_off[i] = ex;
        g_csr[ex] = i;          // self-loop first
        g_cur[i] = ex + 1;
    }
    if (b == SCAN_NB - 1 && t == SCAN_B - 1)
        g_off[NN] = bo + sh[SCAN_B - 1];
}

// ------------------------------------------------------------------
// Fused launch: blocks [0, FB) fill CSR edges; blocks [FB, ...) compute
// layer-0 attention logits (h0 never materialized — agg0 is rank-1).
// ------------------------------------------------------------------
__global__ __launch_bounds__(256) void k_fill_trf0(
    const int* __restrict__ src, const int* __restrict__ dst, int E, int FB,
    const float* __restrict__ x,
    const float* __restrict__ Wg,
    const float* __restrict__ avs,
    const float* __restrict__ avd)
{
    if (blockIdx.x < FB) {
        int i4 = (blockIdx.x * blockDim.x + threadIdx.x) * 4;
        if (i4 + 4 <= E) {
            int4 s = __ldg((const int4*)(src + i4));
            int4 d = __ldg((const int4*)(dst + i4));
            g_csr[atomicAdd(&g_cur[d.x], 1)] = s.x;
            g_csr[atomicAdd(&g_cur[d.y], 1)] = s.y;
            g_csr[atomicAdd(&g_cur[d.z], 1)] = s.z;
            g_csr[atomicAdd(&g_cur[d.w], 1)] = s.w;
        } else {
            for (int i = i4; i < E; i++) {
                int s = __ldg(src + i), d = __ldg(dst + i);
                g_csr[atomicAdd(&g_cur[d], 1)] = s;
            }
        }
        return;
    }

    __shared__ float Ws[64];
    __shared__ float As[64], Ad[64];
    __shared__ unsigned bmax[4];
    int t = threadIdx.x;
    if (t < 64) { Ws[t] = Wg[t]; As[t] = avs[t]; Ad[t] = avd[t]; }
    if (t < 4)  bmax[t] = 0u;
    __syncthreads();

    int lane = t & 31;
    int c0   = lane * 2;
    int n0 = (blockIdx.x - FB) * 32 + (t >> 5) * 4;

    #pragma unroll
    for (int r = 0; r < 4; r++) {
        int n = n0 + r;
        if (n >= NN) break;
        float xv = __ldg(x + n);
        float a0 = xv * Ws[c0];
        float a1 = xv * Ws[c0 + 1];
        float ps = a0 * As[c0] + a1 * As[c0 + 1];
        float pd = a0 * Ad[c0] + a1 * Ad[c0 + 1];
        #pragma unroll
        for (int o = 4; o >= 1; o >>= 1) {
            ps += __shfl_down_sync(0xffffffffu, ps, o);
            pd += __shfl_down_sync(0xffffffffu, pd, o);
        }
        if ((lane & 7) == 0) {
            int hd = lane >> 3;
            g_es[n * 4 + hd] = ps;
            g_ed[n * 4 + hd] = pd;
            atomicMax(&bmax[hd], fenc(ps));
        }
    }
    __syncthreads();
    if (t < 4) atomicMax(&g_gmax[t], bmax[t]);
}

// ------------------------------------------------------------------
// Layer-0 aggregate, rank-1 exact factorization, csr prefetch.
// Output to g_fa (fp16).
// ------------------------------------------------------------------
__global__ __launch_bounds__(256) void k_agg0(
    const float* __restrict__ x,
    const float* __restrict__ W0,
    const float* __restrict__ b0)
{
    int t    = threadIdx.x;
    int lane = t & 31;
    int l16  = lane & 15;
    int hb   = lane & 16;
    unsigned hmask = 0xFFFFu << hb;
    int n = blockIdx.x * 16 + (t >> 4);
    if (n >= NN) return;

    int hd = l16 >> 2;
    int q0 = l16 * 4;
    int beg = __ldg(&g_off[n]), end = __ldg(&g_off[n + 1]);
    float edv = __ldg(&g_ed[n * 4 + hd]);
    float m = leaky02(fdec(g_gmax[hd]) + edv);

    float s = 0.f, ax = 0.f;
    int rem0 = end - beg;
    int myidx = __ldg(&g_csr[beg + (l16 < rem0 ? l16 : 0)]);
    for (int base = beg; base < end; base += 16) {
        int rem = end - base;
        int cnt = rem < 16 ? rem : 16;
        int nb = base + 16;
        int nidx = myidx;
        if (nb < end) {
            int nrem = end - nb;
            nidx = __ldg(&g_csr[nb + (l16 < nrem ? l16 : 0)]);
        }
        int j = 0;
        for (; j + 8 <= cnt; j += 8) {
            int sc[8]; float ev[8], xs[8];
            #pragma unroll
            for (int q = 0; q < 8; q++)
                sc[q] = __shfl_sync(hmask, myidx, hb + j + q);
            #pragma unroll
            for (int q = 0; q < 8; q++) {
                ev[q] = __ldg(&g_es[sc[q] * 4 + hd]);
                xs[q] = __ldg(x + sc[q]);
            }
            #pragma unroll
            for (int q = 0; q < 8; q++) {
                float w = __expf(leaky02(ev[q] + edv) - m);
                s  += w;
                ax += w * xs[q];
            }
        }
        if (j + 4 <= cnt) {
            int sc[4]; float ev[4], xs[4];
            #pragma unroll
            for (int q = 0; q < 4; q++)
                sc[q] = __shfl_sync(hmask, myidx, hb + j + q);
            #pragma unroll
            for (int q = 0; q < 4; q++) {
                ev[q] = __ldg(&g_es[sc[q] * 4 + hd]);
                xs[q] = __ldg(x + sc[q]);
            }
            #pragma unroll
            for (int q = 0; q < 4; q++) {
                float w = __expf(leaky02(ev[q] + edv) - m);
                s  += w;
                ax += w * xs[q];
            }
            j += 4;
        }
        for (; j < cnt; j++) {
            int sc = __shfl_sync(hmask, myidx, hb + j);
            float e  = __ldg(&g_es[sc * 4 + hd]);
            float xv = __ldg(x + sc);
            float w = __expf(leaky02(e + edv) - m);
            s  += w;
            ax += w * xv;
        }
        myidx = nidx;
    }
    float val = ax / (s + 1e-16f);
    float4 w4 = __ldg((const float4*)(W0 + q0));
    float4 bv = __ldg((const float4*)(b0 + q0));
    float4 o;
    o.x = val * w4.x + bv.x;
    o.y = val * w4.y + bv.y;
    o.z = val * w4.z + bv.z;
    o.w = val * w4.w + bv.w;
    sth4(g_fa + (size_t)n * 64 + q0, o);
}

// ------------------------------------------------------------------
// Node transform (Fin=64): 4 nodes per warp, hoisted W smem loads.
// fp16 activation input, fp16 h output; es/ed from fp32 accumulators.
// ------------------------------------------------------------------
__global__ __launch_bounds__(256) void k_transform(
    int xin_sel,
    const float* __restrict__ Wg,
    const float* __restrict__ avs,
    const float* __restrict__ avd,
    int layer)
{
    __shared__ float Ws[64 * 64];
    __shared__ float As[64], Ad[64];
    __shared__ unsigned bmax[4];
    const __half* xin = (xin_sel == 1) ? g_fa : g_fb;
    int t = threadIdx.x;
    {
        const float4* W4 = (const float4*)Wg;
        float4* Ws4 = (float4*)Ws;
        for (int i = t; i < 64 * 16; i += blockDim.x) Ws4[i] = __ldg(W4 + i);
    }
    if (t < 64) { As[t] = avs[t]; Ad[t] = avd[t]; }
    if (t < 4)  bmax[t] = 0u;
    __syncthreads();

    int lane = t & 31;
    int c0   = lane * 2;
    int n0 = blockIdx.x * 32 + (t >> 5) * 4;
    int nv = NN - n0; if (nv > 4) nv = 4;

    float acc[4][2];
    #pragma unroll
    for (int r = 0; r < 4; r++) { acc[r][0] = 0.f; acc[r][1] = 0.f; }

    const __half* x0p = xin + (size_t)n0 * 64;
    #pragma unroll
    for (int k = 0; k < 64; k += 4) {
        float2 w0 = *(const float2*)(Ws + (k + 0) * 64 + c0);
        float2 w1 = *(const float2*)(Ws + (k + 1) * 64 + c0);
        float2 w2 = *(const float2*)(Ws + (k + 2) * 64 + c0);
        float2 w3 = *(const float2*)(Ws + (k + 3) * 64 + c0);
        #pragma unroll
        for (int r = 0; r < 4; r++) {
            if (r < nv) {
                float4 xv = ldh4(x0p + r * 64 + k);
                acc[r][0] += xv.x * w0.x; acc[r][1] += xv.x * w0.y;
                acc[r][0] += xv.y * w1.x; acc[r][1] += xv.y * w1.y;
                acc[r][0] += xv.z * w2.x; acc[r][1] += xv.z * w2.y;
                acc[r][0] += xv.w * w3.x; acc[r][1] += xv.w * w3.y;
            }
        }
    }

    #pragma unroll
    for (int r = 0; r < 4; r++) {
        if (r >= nv) break;
        int n = n0 + r;
        float a0 = acc[r][0], a1 = acc[r][1];
        *(__half2*)(g_h + (size_t)n * 64 + c0) = __floats2half2_rn(a0, a1);
        float ps = a0 * As[c0] + a1 * As[c0 + 1];
        float pd = a0 * Ad[c0] + a1 * Ad[c0 + 1];
        #pragma unroll
        for (int o = 4; o >= 1; o >>= 1) {
            ps += __shfl_down_sync(0xffffffffu, ps, o);
            pd += __shfl_down_sync(0xffffffffu, pd, o);
        }
        if ((lane & 7) == 0) {
            int hd = lane >> 3;
            g_es[n * 4 + hd] = ps;
            g_ed[n * 4 + hd] = pd;
            atomicMax(&bmax[hd], fenc(ps));
        }
    }
    __syncthreads();
    if (t < 4) atomicMax(&g_gmax[layer * 4 + t], bmax[t]);
}

// ------------------------------------------------------------------
// Half-warp single-pass softmax aggregation; fp16 h gather (128B/row).
// ------------------------------------------------------------------
__device__ __forceinline__ float4 agg_node16(
    int n, int l16, int hb, unsigned hmask, int layer,
    const float* __restrict__ bias)
{
    int hd = l16 >> 2;
    int q0 = l16 * 4;
    int beg = __ldg(&g_off[n]), end = __ldg(&g_off[n + 1]);
    float edv = __ldg(&g_ed[n * 4 + hd]);
    float m = leaky02(fdec(g_gmax[layer * 4 + hd]) + edv);

    float s = 0.f;
    float a0 = 0.f, a1 = 0.f, a2 = 0.f, a3 = 0.f;
    int rem0 = end - beg;
    int myidx = __ldg(&g_csr[beg + (l16 < rem0 ? l16 : 0)]);
    for (int base = beg; base < end; base += 16) {
        int rem = end - base;
        int cnt = rem < 16 ? rem : 16;
        int nb = base + 16;
        int nidx = myidx;
        if (nb < end) {
            int nrem = end - nb;
            nidx = __ldg(&g_csr[nb + (l16 < nrem ? l16 : 0)]);
        }
        int j = 0;
        for (; j + 8 <= cnt; j += 8) {
            int sc[8]; float ev[8]; float4 hv[8];
            #pragma unroll
            for (int q = 0; q < 8; q++)
                sc[q] = __shfl_sync(hmask, myidx, hb + j + q);
            #pragma unroll
            for (int q = 0; q < 8; q++) {
                ev[q] = __ldg(&g_es[sc[q] * 4 + hd]);
                hv[q] = ldh4(g_h + (size_t)sc[q] * 64 + q0);
            }
            #pragma unroll
            for (int q = 0; q < 8; q++) {
                float w = __expf(leaky02(ev[q] + edv) - m);
                s  += w;
                a0 += w * hv[q].x; a1 += w * hv[q].y;
                a2 += w * hv[q].z; a3 += w * hv[q].w;
            }
        }
        if (j + 4 <= cnt) {
            int sc[4]; float ev[4]; float4 hv[4];
            #pragma unroll
            for (int q = 0; q < 4; q++)
                sc[q] = __shfl_sync(hmask, myidx, hb + j + q);
            #pragma unroll
            for (int q = 0; q < 4; q++) {
                ev[q] = __ldg(&g_es[sc[q] * 4 + hd]);
                hv[q] = ldh4(g_h + (size_t)sc[q] * 64 + q0);
            }
            #pragma unroll
            for (int q = 0; q < 4; q++) {
                float w = __expf(leaky02(ev[q] + edv) - m);
                s  += w;
                a0 += w * hv[q].x; a1 += w * hv[q].y;
                a2 += w * hv[q].z; a3 += w * hv[q].w;
            }
            j += 4;
        }
        for (; j < cnt; j++) {
            int sc = __shfl_sync(hmask, myidx, hb + j);
            float  e  = __ldg(&g_es[sc * 4 + hd]);
            float4 hv = ldh4(g_h + (size_t)sc * 64 + q0);
            float w = __expf(leaky02(e + edv) - m);
            s  += w;
            a0 += w * hv.x; a1 += w * hv.y;
            a2 += w * hv.z; a3 += w * hv.w;
        }
        myidx = nidx;
    }
    float inv = 1.f / (s + 1e-16f);
    float4 bv = __ldg((const float4*)(bias + q0));
    float4 o;
    o.x = a0 * inv + bv.x;
    o.y = a1 * inv + bv.y;
    o.z = a2 * inv + bv.z;
    o.w = a3 * inv + bv.w;
    return o;
}

// ------------------------------------------------------------------
// Aggregation layer 1 -> g_fb (fp16): half-warp per node
// ------------------------------------------------------------------
__global__ __launch_bounds__(256) void k_aggregate(
    const float* __restrict__ bias, int layer)
{
    int t    = threadIdx.x;
    int lane = t & 31;
    int l16  = lane & 15;
    int hb   = lane & 16;
    unsigned hmask = 0xFFFFu << hb;
    int n = blockIdx.x * 16 + (t >> 4);
    if (n >= NN) return;
    float4 o = agg_node16(n, l16, hb, hmask, layer, bias);
    sth4(g_fb + (size_t)n * 64 + l16 * 4, o);
}

// ------------------------------------------------------------------
// Layer-2 aggregate fused with MLP + decoder + softmax.
// 512 threads = 32 half-warps = 32 nodes/block (3125 blocks exact);
// halves per-block weight staging traffic. No post-work block sync.
// ------------------------------------------------------------------
__global__ __launch_bounds__(512) void k_agg_mlp(
    const float* __restrict__ bias, int layer,
    const float* __restrict__ lw1, const float* __restrict__ lb1,
    const float* __restrict__ lw2, const float* __restrict__ lb2,
    const float* __restrict__ dw,  const float* __restrict__ db,
    float* __restrict__ out)
{
    __shared__ float W1s[64 * 64];
    __shared__ float W2s[64 * 16];
    __shared__ float b1s[64], b2s[16], dws[64], dbs[4];
    __shared__ float t1s[32][68];
    __shared__ float t2s[32][16];
    __shared__ float lgs[32][4];
    int t = threadIdx.x;
    {
        const float4* W14 = (const float4*)lw1;
        float4* W1s4 = (float4*)W1s;
        for (int i = t; i < 64 * 16; i += blockDim.x) W1s4[i] = __ldg(W14 + i);
        const float4* W24 = (const float4*)lw2;
        float4* W2s4 = (float4*)W2s;
        for (int i = t; i < 16 * 16; i += blockDim.x) W2s4[i] = __ldg(W24 + i);
    }
    if (t < 64) b1s[t] = lb1[t];
    if (t < 16) b2s[t] = lb2[t];
    if (t < 64) dws[t] = dw[t];
    if (t < 4)  dbs[t] = db[t];
    __syncthreads();

    int lane = t & 31;
    int l16  = lane & 15;
    int hb   = lane & 16;
    unsigned hmask = 0xFFFFu << hb;
    int hid  = t >> 4;                  // 0..31
    int q0   = l16 * 4;
    int n = blockIdx.x * 32 + hid;      // exact: 3125*32 = 100000

    float4 xr = agg_node16(n, l16, hb, hmask, layer, bias);
    *(float4*)(&t1s[hid][q0]) = xr;
    __syncwarp();

    float a0 = b1s[q0], a1 = b1s[q0 + 1], a2 = b1s[q0 + 2], a3 = b1s[q0 + 3];
    #pragma unroll
    for (int k = 0; k < 64; k++) {
        float xv = t1s[hid][k];
        float4 wv = *(const float4*)(W1s + k * 64 + q0);
        a0 += xv * wv.x; a1 += xv * wv.y;
        a2 += xv * wv.z; a3 += xv * wv.w;
    }
    a0 = a0 > 0.f ? a0 : 0.f;
    a1 = a1 > 0.f ? a1 : 0.f;
    a2 = a2 > 0.f ? a2 : 0.f;
    a3 = a3 > 0.f ? a3 : 0.f;
    __syncwarp();
    t1s[hid][q0]     = a0;
    t1s[hid][q0 + 1] = a1;
    t1s[hid][q0 + 2] = a2;
    t1s[hid][q0 + 3] = a3;
    __syncwarp();

    {
        float acc = b2s[l16];
        #pragma unroll
        for (int k = 0; k < 64; k++) acc += t1s[hid][k] * W2s[k * 16 + l16];
        t2s[hid][l16] = acc;
    }
    __syncwarp();

    if (l16 < 4) {
        float lg = dbs[l16];
        #pragma unroll
        for (int i = 0; i < 16; i++) lg += t2s[hid][i] * dws[i * 4 + l16];
        lgs[hid][l16] = lg;
    }
    __syncwarp();

    if (l16 < 4) {
        float l0 = lgs[hid][0], l1 = lgs[hid][1], l2 = lgs[hid][2], l3 = lgs[hid][3];
        float mx = fmaxf(fmaxf(l0, l1), fmaxf(l2, l3));
        float e0 = __expf(l0 - mx), e1 = __expf(l1 - mx);
        float e2 = __expf(l2 - mx), e3 = __expf(l3 - mx);
        float den = e0 + e1 + e2 + e3;
        float mine = (l16 == 0) ? e0 : (l16 == 1) ? e1 : (l16 == 2) ? e2 : e3;
        out[(size_t)n * 4 + l16] = mine / den;
    }
}

// ------------------------------------------------------------------
extern "C" void kernel_launch(void* const* d_in, const int* in_sizes, int n_in,
                              void* d_out, int out_size)
{
    const float* x   = (const float*)d_in[0];
    const int*   ei  = (const int*)  d_in[1];
    int E = in_sizes[1] / 2;
    const int* src = ei;
    const int* dst = ei + E;
    const float* W0  = (const float*)d_in[2];
    const float* as0 = (const float*)d_in[3];
    const float* ad0 = (const float*)d_in[4];
    const float* b0  = (const float*)d_in[5];
    const float* W1  = (const float*)d_in[6];
    const float* as1 = (const float*)d_in[7];
    const float* ad1 = (const float*)d_in[8];
    const float* b1  = (const float*)d_in[9];
    const float* W2  = (const float*)d_in[10];
    const float* as2 = (const float*)d_in[11];
    const float* ad2 = (const float*)d_in[12];
    const float* b2  = (const float*)d_in[13];
    const float* lw1 = (const float*)d_in[14];
    const float* lb1 = (const float*)d_in[15];
    const float* lw2 = (const float*)d_in[16];
    const float* lb2 = (const float*)d_in[17];
    const float* dw  = (const float*)d_in[18];
    const float* db  = (const float*)d_in[19];
    float* out = (float*)d_out;

    const int AGG16_BLOCKS = (NN + 15) / 16;
    const int AGG32_BLOCKS = NN / 32;         // 3125, exact
    const int TRF_BLOCKS   = (NN + 31) / 32;
    const int NT = 256;
    int FB = (E / 4 + NT - 1) / NT + 1;

    // CSR build
    k_hist<<<FB, NT>>>(dst, E);
    k_scan1<<<SCAN_NB, 256>>>();
    k_scan3<<<SCAN_NB, SCAN_B>>>();
    k_fill_trf0<<<FB + TRF_BLOCKS, NT>>>(src, dst, E, FB, x, W0, as0, ad0);

    // GAT layer 0 aggregate (rank-1 exact) -> g_fa (fp16)
    k_agg0<<<AGG16_BLOCKS, NT>>>(x, W0, b0);
    // GAT layer 1: transform from g_fa, aggregate -> g_fb (fp16)
    k_transform<<<TRF_BLOCKS, NT>>>(1, W1, as1, ad1, 1);
    k_aggregate<<<AGG16_BLOCKS, NT>>>(b1, 1);
    // GAT layer 2: transform from g_fb, fused aggregate + MLP -> out
    k_transform<<<TRF_BLOCKS, NT>>>(2, W2, as2, ad2, 2);
    k_agg_mlp<<<AGG32_BLOCKS, 512>>>(b2, 2, lw1, lb1, lw2, lb2, dw, db, out);
}